// round 10
// baseline (speedup 1.0000x reference)
#include <cuda_runtime.h>
#include <math.h>
#include <stdint.h>

#define B_SZ   8
#define S_LEN  2048
#define HID    256
#define EMBD   256
#define VOC    100
#define BS     (B_SZ * S_LEN)
#define G3     768

typedef unsigned long long ull;

// ---------------- packed f32x2 helpers ----------------
__device__ __forceinline__ void fma2(ull& acc, ull a, ull b) {
    asm("fma.rn.f32x2 %0, %1, %2, %0;" : "+l"(acc) : "l"(a), "l"(b));
}
__device__ __forceinline__ ull pk2(float lo, float hi) {
    ull d; asm("mov.b64 %0, {%1, %2};" : "=l"(d) : "f"(lo), "f"(hi)); return d;
}
__device__ __forceinline__ float2 upk2(ull v) {
    float2 r; asm("mov.b64 {%0, %1}, %2;" : "=f"(r.x), "=f"(r.y) : "l"(v)); return r;
}
__device__ __forceinline__ float sigf_(float x) {
    return 1.0f / (1.0f + __expf(-x));
}
__device__ __forceinline__ unsigned ld_acq(const unsigned* p) {
    unsigned v;
    asm volatile("ld.acquire.gpu.global.u32 %0, [%1];" : "=r"(v) : "l"(p) : "memory");
    return v;
}
__device__ __forceinline__ void rel_flag(unsigned* p, unsigned v) {
    asm volatile("fence.acq_rel.gpu;" ::: "memory");
    asm volatile("st.release.gpu.global.u32 [%0], %1;" :: "l"(p), "r"(v) : "memory");
}

// ---------------- scratch ----------------
__device__ float g_xg[BS * G3];
__device__ float g_h[BS * HID];
__device__ float g_keysT[B_SZ * HID * S_LEN];
__device__ unsigned g_prog[B_SZ][8];
__device__ unsigned g_kflag[B_SZ * 32];

// ---------------------------------------------------------------------------
// SGEMM for xg (proven, used once).
// ---------------------------------------------------------------------------
__global__ void __launch_bounds__(256, 2)
gemm_kernel(const float* __restrict__ A, const int* __restrict__ idx,
            const float* __restrict__ W, const float* __restrict__ bias,
            float* __restrict__ C, int N, int K)
{
    __shared__ __align__(16) float As[8][256];
    __shared__ __align__(16) float Ws[8][128];

    const int bm  = blockIdx.y * 128;
    const int bn  = blockIdx.x * 128;
    const int tid = threadIdx.x;
    const int tx  = tid & 15;
    const int ty  = tid >> 4;
    const int lr  = tid >> 1;
    const int lk  = (tid & 1) << 2;

    ull acc2[8][4];
#pragma unroll
    for (int i = 0; i < 8; i++)
#pragma unroll
        for (int j = 0; j < 4; j++) acc2[i][j] = 0ull;

    int arow = bm + lr;
    if (idx) arow = idx[arow];
    const int wn = bn + lr;

    for (int k0 = 0; k0 < K; k0 += 8) {
        const int kk = k0 + lk;
        float4 av = *(const float4*)(A + (size_t)arow * K + kk);
        *(ull*)&As[lk + 0][2 * lr] = pk2(av.x, av.x);
        *(ull*)&As[lk + 1][2 * lr] = pk2(av.y, av.y);
        *(ull*)&As[lk + 2][2 * lr] = pk2(av.z, av.z);
        *(ull*)&As[lk + 3][2 * lr] = pk2(av.w, av.w);

        float4 wv = make_float4(0.f, 0.f, 0.f, 0.f);
        if (wn < N) wv = *(const float4*)(W + (size_t)wn * K + kk);
        Ws[lk + 0][lr] = wv.x; Ws[lk + 1][lr] = wv.y;
        Ws[lk + 2][lr] = wv.z; Ws[lk + 3][lr] = wv.w;

        __syncthreads();
#pragma unroll
        for (int q = 0; q < 8; q++) {
            ulonglong2 ua0 = *(const ulonglong2*)&As[q][8 * ty];
            ulonglong2 ua1 = *(const ulonglong2*)&As[q][8 * ty + 4];
            ulonglong2 ua2 = *(const ulonglong2*)&As[q][128 + 8 * ty];
            ulonglong2 ua3 = *(const ulonglong2*)&As[q][128 + 8 * ty + 4];
            ulonglong2 ub0 = *(const ulonglong2*)&Ws[q][tx * 4];
            ulonglong2 ub1 = *(const ulonglong2*)&Ws[q][64 + tx * 4];
            ull a2[8] = {ua0.x, ua0.y, ua1.x, ua1.y, ua2.x, ua2.y, ua3.x, ua3.y};
            ull b2[4] = {ub0.x, ub0.y, ub1.x, ub1.y};
#pragma unroll
            for (int i = 0; i < 8; i++)
#pragma unroll
                for (int j = 0; j < 4; j++)
                    fma2(acc2[i][j], a2[i], b2[j]);
        }
        __syncthreads();
    }

#pragma unroll
    for (int i = 0; i < 8; i++) {
        const int r = bm + ((i < 4) ? (ty * 4 + i) : (64 + ty * 4 + i - 4));
        float accr[8];
#pragma unroll
        for (int j = 0; j < 4; j++) {
            float2 f = upk2(acc2[i][j]);
            accr[2 * j] = f.x; accr[2 * j + 1] = f.y;
        }
#pragma unroll
        for (int j = 0; j < 8; j++) {
            const int c = bn + ((j < 4) ? (tx * 4 + j) : (64 + tx * 4 + j - 4));
            if (c < N) C[(size_t)r * N + c] = accr[j] + bias[c];
        }
    }
}

// ---------------------------------------------------------------------------
// k-major microkernel (workers)
// ---------------------------------------------------------------------------
__device__ __forceinline__ void mk_kmajor(const float* __restrict__ At,
                                          const float* __restrict__ Bt,
                                          int i0, int j0, ull (&acc)[4][2])
{
#pragma unroll 4
    for (int k = 0; k < 256; k++) {
        ulonglong2 av = *(const ulonglong2*)(At + k * 68 + i0);
        float4 bv = *(const float4*)(Bt + k * 68 + j0);
        ull b0 = pk2(bv.x, bv.x), b1 = pk2(bv.y, bv.y);
        ull b2 = pk2(bv.z, bv.z), b3 = pk2(bv.w, bv.w);
        fma2(acc[0][0], av.x, b0); fma2(acc[0][1], av.y, b0);
        fma2(acc[1][0], av.x, b1); fma2(acc[1][1], av.y, b1);
        fma2(acc[2][0], av.x, b2); fma2(acc[2][1], av.y, b2);
        fma2(acc[3][0], av.x, b3); fma2(acc[3][1], av.y, b3);
    }
}

__device__ __forceinline__ void loadWT(float* __restrict__ dst,
                                       const float* __restrict__ W,
                                       int rowbase, int rs, int colbase, int tid)
{
    const int n0 = (tid & 15) << 2;
    const int kg = (tid >> 4) << 2;
#pragma unroll
    for (int it = 0; it < 4; it++) {
        const int k4 = kg + (it << 6);
        const float* base = W + (size_t)(rowbase + n0) * rs + colbase + k4;
        float4 v0 = *(const float4*)(base);
        float4 v1 = *(const float4*)(base + rs);
        float4 v2 = *(const float4*)(base + 2 * rs);
        float4 v3 = *(const float4*)(base + 3 * rs);
        *(float4*)(dst + (k4 + 0) * 68 + n0) = make_float4(v0.x, v1.x, v2.x, v3.x);
        *(float4*)(dst + (k4 + 1) * 68 + n0) = make_float4(v0.y, v1.y, v2.y, v3.y);
        *(float4*)(dst + (k4 + 2) * 68 + n0) = make_float4(v0.z, v1.z, v2.z, v3.z);
        *(float4*)(dst + (k4 + 3) * 68 + n0) = make_float4(v0.w, v1.w, v2.w, v3.w);
    }
}

// ---------------------------------------------------------------------------
// MEGA (384 threads): blocks 0..31 GRU (4 clusters x 8 CTAs, 2 batches each);
// blocks 32..287 workers (R8 code).
// ---------------------------------------------------------------------------
#define OFF_QST 0
#define OFF_KST 17408
#define OFF_VS  34816
#define OFF_SS  51456
#define OFF_RM  55808
#define OFF_RL  55872
#define OFF_RA  55936
#define SMEM_BYTES (56000 * 4)

__global__ void __cluster_dims__(8, 1, 1) __launch_bounds__(384, 1)
mega_kernel(const float* __restrict__ xg, const float* __restrict__ w_hh,
            const float* __restrict__ b_hh,
            const float* __restrict__ attn_w, const float* __restrict__ attn_b,
            const float* __restrict__ comb_w, const float* __restrict__ comb_b,
            const float* __restrict__ fc_w, const float* __restrict__ fc_b,
            float* __restrict__ out, float* __restrict__ hid_out)
{
    extern __shared__ float smf[];
    const int tid = threadIdx.x;

    // =============== GRU role: 2 batches per 8-CTA cluster ===============
    if (blockIdx.x < 32) {
        float* hbuf = smf;           // [ba][buf][4 part][68] = 1088 floats
        float* dots = smf + 1088;    // [ba][96]
        float* xgs  = smf + 1280;    // [ba][96]

        unsigned rank;
        asm("mov.u32 %0, %%cluster_ctarank;" : "=r"(rank));
        const int ci = (int)blockIdx.x >> 3;     // cluster 0..3
        const int b0 = ci * 2;                   // batches b0, b0+1
        const int t = tid;
        const int d = t >> 2;           // dot index 0..95
        const int p = t & 3;            // K-part (64 floats)
        const int g = d >> 5, jj = d & 31;
        const int grow = (g << 8) + ((int)rank << 5) + jj;

        ull w2[32];                     // 64 weight floats / thread
        {
            const ulonglong2* wr =
                (const ulonglong2*)(w_hh + (size_t)grow * 256 + (p << 6));
#pragma unroll
            for (int i = 0; i < 16; i++) {
                ulonglong2 v = wr[i];
                w2[2 * i] = v.x; w2[2 * i + 1] = v.y;
            }
        }
        float bhr = 0.f, bhz = 0.f, bhn = 0.f;
        const int myj = ((int)rank << 5) + t;
        if (t < 32) {
            bhr = b_hh[myj]; bhz = b_hh[256 + myj]; bhn = b_hh[512 + myj];
        }
        for (int i = t; i < 1088; i += 384) hbuf[i] = 0.0f;
        __syncthreads();
        asm volatile("barrier.cluster.arrive.aligned;\n\t"
                     "barrier.cluster.wait.aligned;" ::: "memory");

        uint32_t slot00 = 0;   // ba=0, buf=0 local slot
        if (t < 32) {
            slot00 = (uint32_t)__cvta_generic_to_shared(
                hbuf + (myj >> 6) * 68 + (myj & 63));
        }

        const float* xgb0 = xg + (size_t)b0 * S_LEN * G3 + grow;
        const float* xgb1 = xgb0 + (size_t)S_LEN * G3;
        float* hb0 = g_h + (size_t)b0 * S_LEN * HID;
        float* hb1 = hb0 + (size_t)S_LEN * HID;

        float xv0 = (p == 0) ? xgb0[0] : 0.0f;
        float xv1 = (p == 0) ? xgb1[0] : 0.0f;

#pragma unroll 1
        for (int s = 0; s < S_LEN; s++) {
            const int cur = s & 1;
            float xvn0 = 0.0f, xvn1 = 0.0f;
            if (p == 0 && s < S_LEN - 1) {
                xvn0 = xgb0[(size_t)(s + 1) * G3];
                xvn1 = xgb1[(size_t)(s + 1) * G3];
            }

            // ---- dot batch 0 ----
            {
                const ulonglong2* hp =
                    (const ulonglong2*)(hbuf + cur * 272 + p * 68);
                ull a0 = 0ull, a1 = 0ull, a2 = 0ull, a3 = 0ull;
#pragma unroll
                for (int i = 0; i < 8; i++) {
                    ulonglong2 h0 = hp[2 * i], h1 = hp[2 * i + 1];
                    fma2(a0, w2[4 * i + 0], h0.x);
                    fma2(a1, w2[4 * i + 1], h0.y);
                    fma2(a2, w2[4 * i + 2], h1.x);
                    fma2(a3, w2[4 * i + 3], h1.y);
                }
                float2 f0 = upk2(a0), f1 = upk2(a1), f2 = upk2(a2), f3 = upk2(a3);
                float f = ((f0.x + f0.y) + (f1.x + f1.y))
                        + ((f2.x + f2.y) + (f3.x + f3.y));
                f += __shfl_xor_sync(0xffffffffu, f, 1);
                f += __shfl_xor_sync(0xffffffffu, f, 2);
                if (p == 0) { dots[d] = f; xgs[d] = xv0; }
            }
            // ---- dot batch 1 ----
            {
                const ulonglong2* hp =
                    (const ulonglong2*)(hbuf + 544 + cur * 272 + p * 68);
                ull a0 = 0ull, a1 = 0ull, a2 = 0ull, a3 = 0ull;
#pragma unroll
                for (int i = 0; i < 8; i++) {
                    ulonglong2 h0 = hp[2 * i], h1 = hp[2 * i + 1];
                    fma2(a0, w2[4 * i + 0], h0.x);
                    fma2(a1, w2[4 * i + 1], h0.y);
                    fma2(a2, w2[4 * i + 2], h1.x);
                    fma2(a3, w2[4 * i + 3], h1.y);
                }
                float2 f0 = upk2(a0), f1 = upk2(a1), f2 = upk2(a2), f3 = upk2(a3);
                float f = ((f0.x + f0.y) + (f1.x + f1.y))
                        + ((f2.x + f2.y) + (f3.x + f3.y));
                f += __shfl_xor_sync(0xffffffffu, f, 1);
                f += __shfl_xor_sync(0xffffffffu, f, 2);
                if (p == 0) { dots[96 + d] = f; xgs[96 + d] = xv1; }
            }
            __syncthreads();

            if (t < 32) {
#pragma unroll
                for (int ba = 0; ba < 2; ba++) {
                    const int o = ba * 96;
                    const float hr = dots[o + t]      + bhr;
                    const float hz = dots[o + 32 + t] + bhz;
                    const float hn = dots[o + 64 + t] + bhn;
                    const float r = sigf_(xgs[o + t]      + hr);
                    const float z = sigf_(xgs[o + 32 + t] + hz);
                    const float a = xgs[o + 64 + t] + r * hn;
                    const float n = 2.0f * sigf_(2.0f * a) - 1.0f;
                    const float hold =
                        hbuf[ba * 544 + cur * 272 + (myj >> 6) * 68 + (myj & 63)];
                    const float hnew = (1.0f - z) * n + z * hold;
                    float* hbp = ba ? hb1 : hb0;
                    hbp[(size_t)s * HID + myj] = hnew;
                    if (s == S_LEN - 1)
                        hid_out[(b0 + ba) * HID + myj] = hnew;
                    const uint32_t dst = slot00
                        + (uint32_t)ba * 2176u
                        + (uint32_t)(cur ^ 1) * 1088u;
#pragma unroll
                    for (unsigned r8 = 0; r8 < 8; r8++) {
                        uint32_t ra;
                        asm volatile("mapa.shared::cluster.u32 %0, %1, %2;"
                                     : "=r"(ra) : "r"(dst), "r"(r8));
                        asm volatile("st.shared::cluster.f32 [%0], %1;"
                                     :: "r"(ra), "f"(hnew));
                    }
                }
            }
            asm volatile("barrier.cluster.arrive.aligned;\n\t"
                         "barrier.cluster.wait.aligned;" ::: "memory");

            if ((((s + 1) & 31) == 0) && t == 0) {
                rel_flag(&g_prog[b0][rank],     (unsigned)(s + 1));
                rel_flag(&g_prog[b0 + 1][rank], (unsigned)(s + 1));
            }
            xv0 = xvn0; xv1 = xvn1;
        }
        return;
    }

    // =============== worker role (R8 code; threads 0..255 active) ==========
    {
        const bool act = (tid < 256);
        const int w  = (int)blockIdx.x - 32;
        const int qt = w >> 3;
        const int b  = w & 7;
        const int tx = tid & 15;
        const int ty = (tid >> 4) & 15;
        const int i0 = ty * 4;
        const int j0 = tx * 4;

        float* QsT = smf + OFF_QST;
        float* KsT = smf + OFF_KST;
        float* Vs  = smf + OFF_VS;
        float* Ss  = smf + OFF_SS;
        float* rm  = smf + OFF_RM;
        float* rl  = smf + OFF_RL;
        float* ra  = smf + OFF_RA;

        const float* Hb = g_h + (size_t)b * S_LEN * HID;
        float* KgT = g_keysT + (size_t)b * HID * S_LEN;

        if (tid == 0) {
            const unsigned need = (unsigned)(qt + 1) * 64u;
            for (;;) {
                unsigned m = 0xffffffffu;
#pragma unroll
                for (int r = 0; r < 8; r++) {
                    unsigned v = ld_acq(&g_prog[b][r]);
                    m = (v < m) ? v : m;
                }
                if (m >= need) break;
                __nanosleep(256);
            }
        }
        __syncthreads();

        if (act) loadWT(QsT, Hb, qt * 64, HID, 0, tid);
        __syncthreads();

        // ---- phase 1: keys tile qt ----
        for (int c = 0; c < 4; c++) {
            if (act) loadWT(KsT, attn_w, c * 64, 256, 0, tid);
            __syncthreads();
            if (act) {
                ull acc[4][2];
#pragma unroll
                for (int j = 0; j < 4; j++) { acc[j][0] = 0ull; acc[j][1] = 0ull; }
                mk_kmajor(QsT, KsT, i0, j0, acc);
#pragma unroll
                for (int j = 0; j < 4; j++) {
                    const int ng = c * 64 + j0 + j;
                    const float bb = attn_b[ng];
                    float* dst = KgT + (size_t)ng * S_LEN + qt * 64;
#pragma unroll
                    for (int p = 0; p < 2; p++) {
                        float2 f = upk2(acc[j][p]);
                        dst[i0 + 2 * p + 0] = f.x + bb;
                        dst[i0 + 2 * p + 1] = f.y + bb;
                    }
                }
            }
            __syncthreads();
        }
        if (tid == 0) rel_flag(&g_kflag[b * 32 + qt], 1u);

        // ---- phase 2: causal flash attention ----
        if (tid < 64) { rm[tid] = -1e30f; rl[tid] = 0.0f; }
        ull o2[4][8];
#pragma unroll
        for (int i = 0; i < 4; i++)
#pragma unroll
            for (int q = 0; q < 8; q++) o2[i][q] = 0ull;

        for (int kt = qt; kt >= 0; kt--) {
            const bool diag = (kt == qt);
            if (!diag && tid == 0) {
                while (!ld_acq(&g_kflag[b * 32 + kt])) __nanosleep(256);
            }
            __syncthreads();
            if (act) {
#pragma unroll
                for (int it = 0; it < 16; it++) {
                    const int e = it * 256 + tid;
                    const int k = e >> 4, j4 = (e & 15) << 2;
                    *(float4*)(KsT + k * 68 + j4) =
                        *(const float4*)(KgT + (size_t)k * S_LEN + kt * 64 + j4);
                }
#pragma unroll
                for (int it = 0; it < 16; it++) {
                    const int e = it * 256 + tid;
                    const int r = e >> 6, c4 = (e & 63) << 2;
                    *(float4*)(Vs + r * 260 + c4) =
                        *(const float4*)(Hb + (size_t)(kt * 64 + r) * HID + c4);
                }
            }
            __syncthreads();

            if (act) {
                ull acc[4][2];
#pragma unroll
                for (int j = 0; j < 4; j++) { acc[j][0] = 0ull; acc[j][1] = 0ull; }
                mk_kmajor(QsT, KsT, i0, j0, acc);
#pragma unroll
                for (int j = 0; j < 4; j++)
#pragma unroll
                    for (int p = 0; p < 2; p++) {
                        float2 f = upk2(acc[j][p]);
                        const int il0 = i0 + 2 * p;
                        float v0 = f.x, v1 = f.y;
                        if (diag) {
                            if (j0 + j > il0)     v0 = -1e30f;
                            if (j0 + j > il0 + 1) v1 = -1e30f;
                        }
                        Ss[(il0 + 0) * 68 + j0 + j] = v0;
                        Ss[(il0 + 1) * 68 + j0 + j] = v1;
                    }
            }
            __syncthreads();

            if (act) {
                const int row = tid >> 2, qq = tid & 3;
                float* srow = Ss + row * 68 + qq * 16;
                float4 x0 = *(float4*)(srow + 0);
                float4 x1 = *(float4*)(srow + 4);
                float4 x2 = *(float4*)(srow + 8);
                float4 x3 = *(float4*)(srow + 12);
                const float mo = rm[row];
                float mx = fmaxf(fmaxf(fmaxf(x0.x, x0.y), fmaxf(x0.z, x0.w)),
                                 fmaxf(fmaxf(x1.x, x1.y), fmaxf(x1.z, x1.w)));
                mx = fmaxf(mx, fmaxf(fmaxf(fmaxf(x2.x, x2.y), fmaxf(x2.z, x2.w)),
                                     fmaxf(fmaxf(x3.x, x3.y), fmaxf(x3.z, x3.w))));
                mx = fmaxf(mx, __shfl_xor_sync(0xffffffffu, mx, 1));
                mx = fmaxf(mx, __shfl_xor_sync(0xffffffffu, mx, 2));
                mx = fmaxf(mx, mo);
                x0.x = __expf(x0.x - mx); x0.y = __expf(x0.y - mx);
                x0.z = __expf(x0.z - mx); x0.w = __expf(x0.w - mx);
                x1.x = __expf(x1.x - mx); x1.y = __expf(x1.y - mx);
                x1.z = __expf(x1.z - mx); x1.w = __expf(x1.w - mx);
                x2.x = __expf(x2.x - mx); x2.y = __expf(x2.y - mx);
                x2.z = __expf(x2.z - mx); x2.w = __expf(x2.w - mx);
                x3.x = __expf(x3.x - mx); x3.y = __expf(x3.y - mx);
                x3.z = __expf(x3.z - mx); x3.w = __expf(x3.w - mx);
                float sum = (x0.x + x0.y + x0.z + x0.w)
                          + (x1.x + x1.y + x1.z + x1.w)
                          + (x2.x + x2.y + x2.z + x2.w)
                          + (x3.x + x3.y + x3.z + x3.w);
                *(float4*)(srow + 0)  = x0;
                *(float4*)(srow + 4)  = x1;
                *(float4*)(srow + 8)  = x2;
                *(float4*)(srow + 12) = x3;
                sum += __shfl_xor_sync(0xffffffffu, sum, 1);
                sum += __shfl_xor_sync(0xffffffffu, sum, 2);
                if (qq == 0) {
                    const float al = __expf(mo - mx);
                    rm[row] = mx;
                    rl[row] = rl[row] * al + sum;
                    ra[row] = al;
                }
            }
            __syncthreads();

            if (act) {
#pragma unroll
                for (int i = 0; i < 4; i++) {
                    const float al = ra[i0 + i];
                    const ull ald = pk2(al, al);
#pragma unroll
                    for (int q = 0; q < 8; q++) {
                        ull r2;
                        asm("mul.rn.f32x2 %0, %1, %2;" : "=l"(r2)
                            : "l"(o2[i][q]), "l"(ald));
                        o2[i][q] = r2;
                    }
                }
#pragma unroll 2
                for (int j = 0; j < 64; j++) {
                    ull pd[4];
#pragma unroll
                    for (int i = 0; i < 4; i++) {
                        const float pv = Ss[(i0 + i) * 68 + j];
                        pd[i] = pk2(pv, pv);
                    }
                    const float* vrow = Vs + j * 260 + (tx << 2);
#pragma unroll
                    for (int q = 0; q < 4; q++) {
                        ulonglong2 vv = *(const ulonglong2*)(vrow + (q << 6));
#pragma unroll
                        for (int i = 0; i < 4; i++) {
                            fma2(o2[i][2 * q],     pd[i], vv.x);
                            fma2(o2[i][2 * q + 1], pd[i], vv.y);
                        }
                    }
                }
            }
            __syncthreads();
        }

        // ---- phase 3: normalize, ctx -> Vs ----
        if (act) {
#pragma unroll
            for (int i = 0; i < 4; i++) {
                const float inv = 1.0f / rl[i0 + i];
                float* dst = Vs + (i0 + i) * 260 + (tx << 2);
#pragma unroll
                for (int q = 0; q < 4; q++) {
                    float2 lo = upk2(o2[i][2 * q]);
                    float2 hi = upk2(o2[i][2 * q + 1]);
                    *(float4*)(dst + (q << 6)) =
                        make_float4(lo.x * inv, lo.y * inv, hi.x * inv, hi.y * inv);
                }
            }
        }
        __syncthreads();

        // ---- phase 4: comb(tanh) + fc ----
        float facA[4][4], facB[4][4];
#pragma unroll
        for (int i = 0; i < 4; i++)
#pragma unroll
            for (int j = 0; j < 4; j++) { facA[i][j] = 0.f; facB[i][j] = 0.f; }

        for (int c = 0; c < 4; c++) {
            if (act) loadWT(KsT, comb_w, c * 64, 512, 0, tid);
            __syncthreads();
            ull a1[4][2];
#pragma unroll
            for (int j = 0; j < 4; j++) { a1[j][0] = 0ull; a1[j][1] = 0ull; }
            if (act) mk_kmajor(QsT, KsT, i0, j0, a1);
            __syncthreads();
            if (act) loadWT(KsT, comb_w, c * 64, 512, 256, tid);
            __syncthreads();
            if (act) {
                ull a2[4][4];
#pragma unroll
                for (int i = 0; i < 4; i++)
#pragma unroll
                    for (int j = 0; j < 4; j++) a2[i][j] = 0ull;
#pragma unroll 4
                for (int k = 0; k < 256; k += 2) {
                    ull av[4];
#pragma unroll
                    for (int i = 0; i < 4; i++)
                        av[i] = *(const ull*)(Vs + (i0 + i) * 260 + k);
                    ull bv[4];
#pragma unroll
                    for (int j = 0; j < 4; j++)
                        bv[j] = pk2(KsT[k * 68 + j0 + j], KsT[(k + 1) * 68 + j0 + j]);
#pragma unroll
                    for (int i = 0; i < 4; i++)
#pragma unroll
                        for (int j = 0; j < 4; j++)
                            fma2(a2[i][j], av[i], bv[j]);
                }
#pragma unroll
                for (int j = 0; j < 4; j++) {
                    const float cb = comb_b[c * 64 + j0 + j];
#pragma unroll
                    for (int p = 0; p < 2; p++) {
                        float2 f1 = upk2(a1[j][p]);
                        float2 g0 = upk2(a2[2 * p][j]);
                        float2 g1 = upk2(a2[2 * p + 1][j]);
                        Ss[(i0 + 2 * p) * 68 + j0 + j]     = tanhf(f1.x + g0.x + g0.y + cb);
                        Ss[(i0 + 2 * p + 1) * 68 + j0 + j] = tanhf(f1.y + g1.x + g1.y + cb);
                    }
                }
            }
            __syncthreads();
            for (int e = tid; e < 6400; e += 384) {
                const int v = e >> 6, k = e & 63;
                KsT[k * 105 + v] = fc_w[(size_t)v * 256 + c * 64 + k];
            }
            __syncthreads();
            if (act) {
                ull lA[4][4], lB[4][4];
#pragma unroll
                for (int i = 0; i < 4; i++)
#pragma unroll
                    for (int j = 0; j < 4; j++) { lA[i][j] = 0ull; lB[i][j] = 0ull; }
#pragma unroll 4
                for (int k = 0; k < 64; k += 2) {
                    ull av[4];
#pragma unroll
                    for (int i = 0; i < 4; i++)
                        av[i] = *(const ull*)(Ss + (i0 + i) * 68 + k);
#pragma unroll
                    for (int j = 0; j < 4; j++) {
                        const ull bA = pk2(KsT[k * 105 + j0 + j],
                                           KsT[(k + 1) * 105 + j0 + j]);
                        const ull bB = pk2(KsT[k * 105 + 64 + j0 + j],
                                           KsT[(k + 1) * 105 + 64 + j0 + j]);
#pragma unroll
                        for (int i = 0; i < 4; i++) {
                            fma2(lA[i][j], av[i], bA);
                            fma2(lB[i][j], av[i], bB);
                        }
                    }
                }
#pragma unroll
                for (int i = 0; i < 4; i++)
#pragma unroll
                    for (int j = 0; j < 4; j++) {
                        float2 fa = upk2(lA[i][j]); facA[i][j] += fa.x + fa.y;
                        float2 fb = upk2(lB[i][j]); facB[i][j] += fb.x + fb.y;
                    }
            }
            __syncthreads();
        }

        if (act) {
#pragma unroll
            for (int i = 0; i < 4; i++) {
                const size_t row = (size_t)b * S_LEN + qt * 64 + i0 + i;
#pragma unroll
                for (int j = 0; j < 4; j++) {
                    const int vA = j0 + j;
                    out[row * VOC + vA] = facA[i][j] + fc_b[vA];
                    const int vB = 64 + j0 + j;
                    if (vB < VOC)
                        out[row * VOC + vB] = facB[i][j] + fc_b[vB];
                }
            }
        }
    }
}

// ---------------------------------------------------------------------------
extern "C" void kernel_launch(void* const* d_in, const int* in_sizes, int n_in,
                              void* d_out, int out_size)
{
    const int*   x      = (const int*)  d_in[0];
    const float* emb    = (const float*)d_in[1];
    const float* w_ih   = (const float*)d_in[2];
    const float* w_hh   = (const float*)d_in[3];
    const float* b_ih   = (const float*)d_in[4];
    const float* b_hh   = (const float*)d_in[5];
    const float* attn_w = (const float*)d_in[6];
    const float* attn_b = (const float*)d_in[7];
    const float* comb_w = (const float*)d_in[8];
    const float* comb_b = (const float*)d_in[9];
    const float* fc_w   = (const float*)d_in[10];
    const float* fc_b   = (const float*)d_in[11];
    float* out = (float*)d_out;

    float* xg;
    void *progp, *kflagp;
    cudaGetSymbolAddress((void**)&xg, g_xg);
    cudaGetSymbolAddress(&progp,  g_prog);
    cudaGetSymbolAddress(&kflagp, g_kflag);

    cudaMemsetAsync(progp,  0, sizeof(unsigned) * B_SZ * 8);
    cudaMemsetAsync(kflagp, 0, sizeof(unsigned) * B_SZ * 32);

    cudaFuncSetAttribute(mega_kernel,
                         cudaFuncAttributeMaxDynamicSharedMemorySize,
                         SMEM_BYTES);

    gemm_kernel<<<dim3(6, 128), 256>>>(emb, x, w_ih, b_ih, xg, G3, EMBD);

    mega_kernel<<<288, 384, SMEM_BYTES>>>(xg, w_hh, b_hh,
                                          attn_w, attn_b, comb_w, comb_b,
                                          fc_w, fc_b,
                                          out, out + (size_t)BS * VOC);
}

// round 12
// speedup vs baseline: 1.3406x; 1.3406x over previous
#include <cuda_runtime.h>
#include <math.h>
#include <stdint.h>

#define B_SZ   8
#define S_LEN  2048
#define HID    256
#define EMBD   256
#define VOC    100
#define BS     (B_SZ * S_LEN)
#define G3     768

typedef unsigned long long ull;

// ---------------- packed f32x2 helpers ----------------
__device__ __forceinline__ void fma2(ull& acc, ull a, ull b) {
    asm("fma.rn.f32x2 %0, %1, %2, %0;" : "+l"(acc) : "l"(a), "l"(b));
}
__device__ __forceinline__ ull pk2(float lo, float hi) {
    ull d; asm("mov.b64 %0, {%1, %2};" : "=l"(d) : "f"(lo), "f"(hi)); return d;
}
__device__ __forceinline__ float2 upk2(ull v) {
    float2 r; asm("mov.b64 {%0, %1}, %2;" : "=f"(r.x), "=f"(r.y) : "l"(v)); return r;
}
__device__ __forceinline__ float sigf_(float x) {
    return 1.0f / (1.0f + __expf(-x));
}
__device__ __forceinline__ unsigned ld_acq(const unsigned* p) {
    unsigned v;
    asm volatile("ld.acquire.gpu.global.u32 %0, [%1];" : "=r"(v) : "l"(p) : "memory");
    return v;
}
__device__ __forceinline__ void rel_flag(unsigned* p, unsigned v) {
    asm volatile("fence.acq_rel.gpu;" ::: "memory");
    asm volatile("st.release.gpu.global.u32 [%0], %1;" :: "l"(p), "r"(v) : "memory");
}

// ---------------- scratch ----------------
__device__ float g_xg[BS * G3];
__device__ float g_h[BS * HID];
__device__ float g_keysT[B_SZ * HID * S_LEN];
__device__ unsigned g_prog[B_SZ][8];
__device__ unsigned g_kflag[B_SZ * 32];
__device__ unsigned g_xgflag[B_SZ * 32];   // per (batch, 64-token chunk)

// ---------------------------------------------------------------------------
// k-major microkernel: acc[j][p] += sum_k A[k][i0+2p..] * B[k][j0+j]
// ---------------------------------------------------------------------------
__device__ __forceinline__ void mk_kmajor(const float* __restrict__ At,
                                          const float* __restrict__ Bt,
                                          int i0, int j0, ull (&acc)[4][2])
{
#pragma unroll 4
    for (int k = 0; k < 256; k++) {
        ulonglong2 av = *(const ulonglong2*)(At + k * 68 + i0);
        float4 bv = *(const float4*)(Bt + k * 68 + j0);
        ull b0 = pk2(bv.x, bv.x), b1 = pk2(bv.y, bv.y);
        ull b2 = pk2(bv.z, bv.z), b3 = pk2(bv.w, bv.w);
        fma2(acc[0][0], av.x, b0); fma2(acc[0][1], av.y, b0);
        fma2(acc[1][0], av.x, b1); fma2(acc[1][1], av.y, b1);
        fma2(acc[2][0], av.x, b2); fma2(acc[2][1], av.y, b2);
        fma2(acc[3][0], av.x, b3); fma2(acc[3][1], av.y, b3);
    }
}

// Transpose-load: dst[k][n] (stride 68) from row-major W[rowbase+n][colbase+k]
__device__ __forceinline__ void loadWT(float* __restrict__ dst,
                                       const float* __restrict__ W,
                                       int rowbase, int rs, int colbase, int tid)
{
    const int n0 = (tid & 15) << 2;
    const int kg = (tid >> 4) << 2;
#pragma unroll
    for (int it = 0; it < 4; it++) {
        const int k4 = kg + (it << 6);
        const float* base = W + (size_t)(rowbase + n0) * rs + colbase + k4;
        float4 v0 = *(const float4*)(base);
        float4 v1 = *(const float4*)(base + rs);
        float4 v2 = *(const float4*)(base + 2 * rs);
        float4 v3 = *(const float4*)(base + 3 * rs);
        *(float4*)(dst + (k4 + 0) * 68 + n0) = make_float4(v0.x, v1.x, v2.x, v3.x);
        *(float4*)(dst + (k4 + 1) * 68 + n0) = make_float4(v0.y, v1.y, v2.y, v3.y);
        *(float4*)(dst + (k4 + 2) * 68 + n0) = make_float4(v0.z, v1.z, v2.z, v3.z);
        *(float4*)(dst + (k4 + 3) * 68 + n0) = make_float4(v0.w, v1.w, v2.w, v3.w);
    }
}

// Gathered transpose-load: rows come from emb[xrow[n]] (embedding lookup)
__device__ __forceinline__ void loadA_gather(float* __restrict__ dst,
                                             const float* __restrict__ emb,
                                             const int* __restrict__ xrow, int tid)
{
    const int n0 = (tid & 15) << 2;
    const int kg = (tid >> 4) << 2;
    const int r0 = xrow[n0], r1 = xrow[n0 + 1];
    const int r2 = xrow[n0 + 2], r3 = xrow[n0 + 3];
#pragma unroll
    for (int it = 0; it < 4; it++) {
        const int k4 = kg + (it << 6);
        float4 v0 = *(const float4*)(emb + (size_t)r0 * EMBD + k4);
        float4 v1 = *(const float4*)(emb + (size_t)r1 * EMBD + k4);
        float4 v2 = *(const float4*)(emb + (size_t)r2 * EMBD + k4);
        float4 v3 = *(const float4*)(emb + (size_t)r3 * EMBD + k4);
        *(float4*)(dst + (k4 + 0) * 68 + n0) = make_float4(v0.x, v1.x, v2.x, v3.x);
        *(float4*)(dst + (k4 + 1) * 68 + n0) = make_float4(v0.y, v1.y, v2.y, v3.y);
        *(float4*)(dst + (k4 + 2) * 68 + n0) = make_float4(v0.z, v1.z, v2.z, v3.z);
        *(float4*)(dst + (k4 + 3) * 68 + n0) = make_float4(v0.w, v1.w, v2.w, v3.w);
    }
}

// ---------------------------------------------------------------------------
// MEGA (384 threads): blocks 0..63 GRU; 64..127 xg producers; 128..383 workers.
// ---------------------------------------------------------------------------
#define OFF_QST 0
#define OFF_KST 17408
#define OFF_VS  34816
#define OFF_SS  51456
#define OFF_RM  55808
#define OFF_RL  55872
#define OFF_RA  55936
#define SMEM_BYTES (56000 * 4)

__global__ void __cluster_dims__(8, 1, 1) __launch_bounds__(384, 1)
mega_kernel(const int* __restrict__ x, const float* __restrict__ emb,
            const float* __restrict__ w_ih, const float* __restrict__ b_ih,
            const float* __restrict__ w_hh, const float* __restrict__ b_hh,
            const float* __restrict__ attn_w, const float* __restrict__ attn_b,
            const float* __restrict__ comb_w, const float* __restrict__ comb_b,
            const float* __restrict__ fc_w, const float* __restrict__ fc_b,
            float* __restrict__ out, float* __restrict__ hid_out)
{
    extern __shared__ float smf[];
    const int tid = threadIdx.x;

    // =============== GRU role (R8, + xg chunk-flag spin) ===============
    if (blockIdx.x < 64) {
        float* hbuf = smf;          // [2 buf][4 part][68]
        float* dots = smf + 544;
        float* xgs  = smf + 640;

        unsigned rank;
        asm("mov.u32 %0, %%cluster_ctarank;" : "=r"(rank));
        const int b = (int)blockIdx.x >> 3;
        const int t = tid;
        const int d = t >> 2;
        const int p = t & 3;
        const int g = d >> 5, jj = d & 31;
        const int grow = (g << 8) + ((int)rank << 5) + jj;

        ull w2[32];
        {
            const ulonglong2* wr =
                (const ulonglong2*)(w_hh + (size_t)grow * 256 + (p << 6));
#pragma unroll
            for (int i = 0; i < 16; i++) {
                ulonglong2 v = wr[i];
                w2[2 * i] = v.x; w2[2 * i + 1] = v.y;
            }
        }
        float bhr = 0.f, bhz = 0.f, bhn = 0.f;
        const int myj = ((int)rank << 5) + t;
        if (t < 32) {
            bhr = b_hh[myj]; bhz = b_hh[256 + myj]; bhn = b_hh[512 + myj];
        }
        for (int i = t; i < 544; i += 384) hbuf[i] = 0.0f;
        __syncthreads();
        asm volatile("barrier.cluster.arrive.aligned;\n\t"
                     "barrier.cluster.wait.aligned;" ::: "memory");

        uint32_t slot0 = 0, slot1 = 0;
        if (t < 32) {
            slot0 = (uint32_t)__cvta_generic_to_shared(
                hbuf + (myj >> 6) * 68 + (myj & 63));
            slot1 = slot0 + 272u * 4u;
        }

        const float* xgbase = g_xg + (size_t)b * S_LEN * G3 + grow;
        float* hb = g_h + (size_t)b * S_LEN * HID;

        float xv = 0.0f;
        if (p == 0) {
            while (!ld_acq(&g_xgflag[b * 32])) __nanosleep(128);
            xv = xgbase[0];
        }

#pragma unroll 1
        for (int s = 0; s < S_LEN; s++) {
            const int cur = s & 1;
            float xvn = 0.0f;
            if (p == 0 && s < S_LEN - 1) {
                const int sn = s + 1;
                if ((sn & 63) == 0) {
                    while (!ld_acq(&g_xgflag[b * 32 + (sn >> 6)]))
                        __nanosleep(128);
                }
                xvn = xgbase[(size_t)sn * G3];
            }

            {
                const ulonglong2* hp =
                    (const ulonglong2*)(hbuf + cur * 272 + p * 68);
                ull a0 = 0ull, a1 = 0ull, a2 = 0ull, a3 = 0ull;
#pragma unroll
                for (int i = 0; i < 8; i++) {
                    ulonglong2 h0 = hp[2 * i], h1 = hp[2 * i + 1];
                    fma2(a0, w2[4 * i + 0], h0.x);
                    fma2(a1, w2[4 * i + 1], h0.y);
                    fma2(a2, w2[4 * i + 2], h1.x);
                    fma2(a3, w2[4 * i + 3], h1.y);
                }
                float2 f0 = upk2(a0), f1 = upk2(a1), f2 = upk2(a2), f3 = upk2(a3);
                float f = ((f0.x + f0.y) + (f1.x + f1.y))
                        + ((f2.x + f2.y) + (f3.x + f3.y));
                f += __shfl_xor_sync(0xffffffffu, f, 1);
                f += __shfl_xor_sync(0xffffffffu, f, 2);
                if (p == 0) { dots[d] = f; xgs[d] = xv; }
            }
            __syncthreads();

            if (t < 32) {
                const float hr = dots[t]      + bhr;
                const float hz = dots[32 + t] + bhz;
                const float hn = dots[64 + t] + bhn;
                const float r = sigf_(xgs[t]      + hr);
                const float z = sigf_(xgs[32 + t] + hz);
                const float a = xgs[64 + t] + r * hn;
                const float n = 2.0f * sigf_(2.0f * a) - 1.0f;
                const float hold = hbuf[cur * 272 + (myj >> 6) * 68 + (myj & 63)];
                const float hnew = (1.0f - z) * n + z * hold;
                hb[(size_t)s * HID + myj] = hnew;
                if (s == S_LEN - 1) hid_out[b * HID + myj] = hnew;
                const uint32_t dst = (cur == 0) ? slot1 : slot0;
#pragma unroll
                for (unsigned r8 = 0; r8 < 8; r8++) {
                    uint32_t ra;
                    asm volatile("mapa.shared::cluster.u32 %0, %1, %2;"
                                 : "=r"(ra) : "r"(dst), "r"(r8));
                    asm volatile("st.shared::cluster.f32 [%0], %1;"
                                 :: "r"(ra), "f"(hnew));
                }
            }
            asm volatile("barrier.cluster.arrive.aligned;\n\t"
                         "barrier.cluster.wait.aligned;" ::: "memory");

            if ((((s + 1) & 31) == 0) && t == 0)
                rel_flag(&g_prog[b][rank], (unsigned)(s + 1));
            xv = xvn;
        }
        return;
    }

    // =============== xg producer role: blocks 64..127 ===============
    if (blockIdx.x < 128) {
        const bool act = (tid < 256);
        const int w2i = (int)blockIdx.x - 64;
        const int b  = w2i & 7;
        const int ib = w2i >> 3;             // 0..7
        const int tx = tid & 15;
        const int ty = (tid >> 4) & 15;
        const int i0 = ty * 4;
        const int j0 = tx * 4;

        float* At = smf + OFF_QST;           // emb tile, k-major [256][68]
        float* Wt = smf + OFF_KST;           // w_ih tile, k-major

        const int* xb = x + b * S_LEN;

        for (int ch = ib; ch < 32; ch += 8) {
            if (act) loadA_gather(At, emb, xb + ch * 64, tid);
            __syncthreads();
            for (int nc = 0; nc < 12; nc++) {
                if (act) loadWT(Wt, w_ih, nc * 64, 256, 0, tid);
                __syncthreads();
                if (act) {
                    ull acc[4][2];
#pragma unroll
                    for (int j = 0; j < 4; j++) { acc[j][0] = 0ull; acc[j][1] = 0ull; }
                    mk_kmajor(At, Wt, i0, j0, acc);
#pragma unroll
                    for (int j = 0; j < 4; j++) {
                        const int col = nc * 64 + j0 + j;
                        const float bb = b_ih[col];
#pragma unroll
                        for (int p = 0; p < 2; p++) {
                            float2 f = upk2(acc[j][p]);
                            const size_t row =
                                (size_t)b * S_LEN + ch * 64 + i0 + 2 * p;
                            g_xg[row * G3 + col]       = f.x + bb;
                            g_xg[(row + 1) * G3 + col] = f.y + bb;
                        }
                    }
                }
                __syncthreads();
            }
            if (tid == 0) rel_flag(&g_xgflag[b * 32 + ch], 1u);
        }
        return;
    }

    // =============== worker role (R8, unchanged; threads 0..255) ===========
    {
        const bool act = (tid < 256);
        const int w  = (int)blockIdx.x - 128;
        const int qt = w >> 3;
        const int b  = w & 7;
        const int tx = tid & 15;
        const int ty = (tid >> 4) & 15;
        const int i0 = ty * 4;
        const int j0 = tx * 4;

        float* QsT = smf + OFF_QST;
        float* KsT = smf + OFF_KST;
        float* Vs  = smf + OFF_VS;
        float* Ss  = smf + OFF_SS;
        float* rm  = smf + OFF_RM;
        float* rl  = smf + OFF_RL;
        float* ra  = smf + OFF_RA;

        const float* Hb = g_h + (size_t)b * S_LEN * HID;
        float* KgT = g_keysT + (size_t)b * HID * S_LEN;

        if (tid == 0) {
            const unsigned need = (unsigned)(qt + 1) * 64u;
            for (;;) {
                unsigned m = 0xffffffffu;
#pragma unroll
                for (int r = 0; r < 8; r++) {
                    unsigned v = ld_acq(&g_prog[b][r]);
                    m = (v < m) ? v : m;
                }
                if (m >= need) break;
                __nanosleep(256);
            }
        }
        __syncthreads();

        if (act) loadWT(QsT, Hb, qt * 64, HID, 0, tid);
        __syncthreads();

        // ---- phase 1: keys tile qt ----
        for (int c = 0; c < 4; c++) {
            if (act) loadWT(KsT, attn_w, c * 64, 256, 0, tid);
            __syncthreads();
            if (act) {
                ull acc[4][2];
#pragma unroll
                for (int j = 0; j < 4; j++) { acc[j][0] = 0ull; acc[j][1] = 0ull; }
                mk_kmajor(QsT, KsT, i0, j0, acc);
#pragma unroll
                for (int j = 0; j < 4; j++) {
                    const int ng = c * 64 + j0 + j;
                    const float bb = attn_b[ng];
                    float* dst = KgT + (size_t)ng * S_LEN + qt * 64;
#pragma unroll
                    for (int p = 0; p < 2; p++) {
                        float2 f = upk2(acc[j][p]);
                        dst[i0 + 2 * p + 0] = f.x + bb;
                        dst[i0 + 2 * p + 1] = f.y + bb;
                    }
                }
            }
            __syncthreads();
        }
        if (tid == 0) rel_flag(&g_kflag[b * 32 + qt], 1u);

        // ---- phase 2: causal flash attention ----
        if (tid < 64) { rm[tid] = -1e30f; rl[tid] = 0.0f; }
        ull o2[4][8];
#pragma unroll
        for (int i = 0; i < 4; i++)
#pragma unroll
            for (int q = 0; q < 8; q++) o2[i][q] = 0ull;

        for (int kt = qt; kt >= 0; kt--) {
            const bool diag = (kt == qt);
            if (!diag && tid == 0) {
                while (!ld_acq(&g_kflag[b * 32 + kt])) __nanosleep(256);
            }
            __syncthreads();
            if (act) {
#pragma unroll
                for (int it = 0; it < 16; it++) {
                    const int e = it * 256 + tid;
                    const int k = e >> 4, j4 = (e & 15) << 2;
                    *(float4*)(KsT + k * 68 + j4) =
                        *(const float4*)(KgT + (size_t)k * S_LEN + kt * 64 + j4);
                }
#pragma unroll
                for (int it = 0; it < 16; it++) {
                    const int e = it * 256 + tid;
                    const int r = e >> 6, c4 = (e & 63) << 2;
                    *(float4*)(Vs + r * 260 + c4) =
                        *(const float4*)(Hb + (size_t)(kt * 64 + r) * HID + c4);
                }
            }
            __syncthreads();

            if (act) {
                ull acc[4][2];
#pragma unroll
                for (int j = 0; j < 4; j++) { acc[j][0] = 0ull; acc[j][1] = 0ull; }
                mk_kmajor(QsT, KsT, i0, j0, acc);
#pragma unroll
                for (int j = 0; j < 4; j++)
#pragma unroll
                    for (int p = 0; p < 2; p++) {
                        float2 f = upk2(acc[j][p]);
                        const int il0 = i0 + 2 * p;
                        float v0 = f.x, v1 = f.y;
                        if (diag) {
                            if (j0 + j > il0)     v0 = -1e30f;
                            if (j0 + j > il0 + 1) v1 = -1e30f;
                        }
                        Ss[(il0 + 0) * 68 + j0 + j] = v0;
                        Ss[(il0 + 1) * 68 + j0 + j] = v1;
                    }
            }
            __syncthreads();

            if (act) {
                const int row = tid >> 2, qq = tid & 3;
                float* srow = Ss + row * 68 + qq * 16;
                float4 x0 = *(float4*)(srow + 0);
                float4 x1 = *(float4*)(srow + 4);
                float4 x2 = *(float4*)(srow + 8);
                float4 x3 = *(float4*)(srow + 12);
                const float mo = rm[row];
                float mx = fmaxf(fmaxf(fmaxf(x0.x, x0.y), fmaxf(x0.z, x0.w)),
                                 fmaxf(fmaxf(x1.x, x1.y), fmaxf(x1.z, x1.w)));
                mx = fmaxf(mx, fmaxf(fmaxf(fmaxf(x2.x, x2.y), fmaxf(x2.z, x2.w)),
                                     fmaxf(fmaxf(x3.x, x3.y), fmaxf(x3.z, x3.w))));
                mx = fmaxf(mx, __shfl_xor_sync(0xffffffffu, mx, 1));
                mx = fmaxf(mx, __shfl_xor_sync(0xffffffffu, mx, 2));
                mx = fmaxf(mx, mo);
                x0.x = __expf(x0.x - mx); x0.y = __expf(x0.y - mx);
                x0.z = __expf(x0.z - mx); x0.w = __expf(x0.w - mx);
                x1.x = __expf(x1.x - mx); x1.y = __expf(x1.y - mx);
                x1.z = __expf(x1.z - mx); x1.w = __expf(x1.w - mx);
                x2.x = __expf(x2.x - mx); x2.y = __expf(x2.y - mx);
                x2.z = __expf(x2.z - mx); x2.w = __expf(x2.w - mx);
                x3.x = __expf(x3.x - mx); x3.y = __expf(x3.y - mx);
                x3.z = __expf(x3.z - mx); x3.w = __expf(x3.w - mx);
                float sum = (x0.x + x0.y + x0.z + x0.w)
                          + (x1.x + x1.y + x1.z + x1.w)
                          + (x2.x + x2.y + x2.z + x2.w)
                          + (x3.x + x3.y + x3.z + x3.w);
                *(float4*)(srow + 0)  = x0;
                *(float4*)(srow + 4)  = x1;
                *(float4*)(srow + 8)  = x2;
                *(float4*)(srow + 12) = x3;
                sum += __shfl_xor_sync(0xffffffffu, sum, 1);
                sum += __shfl_xor_sync(0xffffffffu, sum, 2);
                if (qq == 0) {
                    const float al = __expf(mo - mx);
                    rm[row] = mx;
                    rl[row] = rl[row] * al + sum;
                    ra[row] = al;
                }
            }
            __syncthreads();

            if (act) {
#pragma unroll
                for (int i = 0; i < 4; i++) {
                    const float al = ra[i0 + i];
                    const ull ald = pk2(al, al);
#pragma unroll
                    for (int q = 0; q < 8; q++) {
                        ull r2;
                        asm("mul.rn.f32x2 %0, %1, %2;" : "=l"(r2)
                            : "l"(o2[i][q]), "l"(ald));
                        o2[i][q] = r2;
                    }
                }
#pragma unroll 2
                for (int j = 0; j < 64; j++) {
                    ull pd[4];
#pragma unroll
                    for (int i = 0; i < 4; i++) {
                        const float pv = Ss[(i0 + i) * 68 + j];
                        pd[i] = pk2(pv, pv);
                    }
                    const float* vrow = Vs + j * 260 + (tx << 2);
#pragma unroll
                    for (int q = 0; q < 4; q++) {
                        ulonglong2 vv = *(const ulonglong2*)(vrow + (q << 6));
#pragma unroll
                        for (int i = 0; i < 4; i++) {
                            fma2(o2[i][2 * q],     pd[i], vv.x);
                            fma2(o2[i][2 * q + 1], pd[i], vv.y);
                        }
                    }
                }
            }
            __syncthreads();
        }

        // ---- phase 3: normalize, ctx -> Vs ----
        if (act) {
#pragma unroll
            for (int i = 0; i < 4; i++) {
                const float inv = 1.0f / rl[i0 + i];
                float* dst = Vs + (i0 + i) * 260 + (tx << 2);
#pragma unroll
                for (int q = 0; q < 4; q++) {
                    float2 lo = upk2(o2[i][2 * q]);
                    float2 hi = upk2(o2[i][2 * q + 1]);
                    *(float4*)(dst + (q << 6)) =
                        make_float4(lo.x * inv, lo.y * inv, hi.x * inv, hi.y * inv);
                }
            }
        }
        __syncthreads();

        // ---- phase 4: comb(tanh) + fc ----
        float facA[4][4], facB[4][4];
#pragma unroll
        for (int i = 0; i < 4; i++)
#pragma unroll
            for (int j = 0; j < 4; j++) { facA[i][j] = 0.f; facB[i][j] = 0.f; }

        for (int c = 0; c < 4; c++) {
            if (act) loadWT(KsT, comb_w, c * 64, 512, 0, tid);
            __syncthreads();
            ull a1[4][2];
#pragma unroll
            for (int j = 0; j < 4; j++) { a1[j][0] = 0ull; a1[j][1] = 0ull; }
            if (act) mk_kmajor(QsT, KsT, i0, j0, a1);
            __syncthreads();
            if (act) loadWT(KsT, comb_w, c * 64, 512, 256, tid);
            __syncthreads();
            if (act) {
                ull a2[4][4];
#pragma unroll
                for (int i = 0; i < 4; i++)
#pragma unroll
                    for (int j = 0; j < 4; j++) a2[i][j] = 0ull;
#pragma unroll 4
                for (int k = 0; k < 256; k += 2) {
                    ull av[4];
#pragma unroll
                    for (int i = 0; i < 4; i++)
                        av[i] = *(const ull*)(Vs + (i0 + i) * 260 + k);
                    ull bv[4];
#pragma unroll
                    for (int j = 0; j < 4; j++)
                        bv[j] = pk2(KsT[k * 68 + j0 + j], KsT[(k + 1) * 68 + j0 + j]);
#pragma unroll
                    for (int i = 0; i < 4; i++)
#pragma unroll
                        for (int j = 0; j < 4; j++)
                            fma2(a2[i][j], av[i], bv[j]);
                }
#pragma unroll
                for (int j = 0; j < 4; j++) {
                    const float cb = comb_b[c * 64 + j0 + j];
#pragma unroll
                    for (int p = 0; p < 2; p++) {
                        float2 f1 = upk2(a1[j][p]);
                        float2 g0 = upk2(a2[2 * p][j]);
                        float2 g1 = upk2(a2[2 * p + 1][j]);
                        Ss[(i0 + 2 * p) * 68 + j0 + j]     = tanhf(f1.x + g0.x + g0.y + cb);
                        Ss[(i0 + 2 * p + 1) * 68 + j0 + j] = tanhf(f1.y + g1.x + g1.y + cb);
                    }
                }
            }
            __syncthreads();
            for (int e = tid; e < 6400; e += 384) {
                const int v = e >> 6, k = e & 63;
                KsT[k * 105 + v] = fc_w[(size_t)v * 256 + c * 64 + k];
            }
            __syncthreads();
            if (act) {
                ull lA[4][4], lB[4][4];
#pragma unroll
                for (int i = 0; i < 4; i++)
#pragma unroll
                    for (int j = 0; j < 4; j++) { lA[i][j] = 0ull; lB[i][j] = 0ull; }
#pragma unroll 4
                for (int k = 0; k < 64; k += 2) {
                    ull av[4];
#pragma unroll
                    for (int i = 0; i < 4; i++)
                        av[i] = *(const ull*)(Ss + (i0 + i) * 68 + k);
#pragma unroll
                    for (int j = 0; j < 4; j++) {
                        const ull bA = pk2(KsT[k * 105 + j0 + j],
                                           KsT[(k + 1) * 105 + j0 + j]);
                        const ull bB = pk2(KsT[k * 105 + 64 + j0 + j],
                                           KsT[(k + 1) * 105 + 64 + j0 + j]);
#pragma unroll
                        for (int i = 0; i < 4; i++) {
                            fma2(lA[i][j], av[i], bA);
                            fma2(lB[i][j], av[i], bB);
                        }
                    }
                }
#pragma unroll
                for (int i = 0; i < 4; i++)
#pragma unroll
                    for (int j = 0; j < 4; j++) {
                        float2 fa = upk2(lA[i][j]); facA[i][j] += fa.x + fa.y;
                        float2 fb = upk2(lB[i][j]); facB[i][j] += fb.x + fb.y;
                    }
            }
            __syncthreads();
        }

        if (act) {
#pragma unroll
            for (int i = 0; i < 4; i++) {
                const size_t row = (size_t)b * S_LEN + qt * 64 + i0 + i;
#pragma unroll
                for (int j = 0; j < 4; j++) {
                    const int vA = j0 + j;
                    out[row * VOC + vA] = facA[i][j] + fc_b[vA];
                    const int vB = 64 + j0 + j;
                    if (vB < VOC)
                        out[row * VOC + vB] = facB[i][j] + fc_b[vB];
                }
            }
        }
    }
}

// ---------------------------------------------------------------------------
extern "C" void kernel_launch(void* const* d_in, const int* in_sizes, int n_in,
                              void* d_out, int out_size)
{
    const int*   x      = (const int*)  d_in[0];
    const float* emb    = (const float*)d_in[1];
    const float* w_ih   = (const float*)d_in[2];
    const float* w_hh   = (const float*)d_in[3];
    const float* b_ih   = (const float*)d_in[4];
    const float* b_hh   = (const float*)d_in[5];
    const float* attn_w = (const float*)d_in[6];
    const float* attn_b = (const float*)d_in[7];
    const float* comb_w = (const float*)d_in[8];
    const float* comb_b = (const float*)d_in[9];
    const float* fc_w   = (const float*)d_in[10];
    const float* fc_b   = (const float*)d_in[11];
    float* out = (float*)d_out;

    void *progp, *kflagp, *xgflagp;
    cudaGetSymbolAddress(&progp,   g_prog);
    cudaGetSymbolAddress(&kflagp,  g_kflag);
    cudaGetSymbolAddress(&xgflagp, g_xgflag);

    cudaMemsetAsync(progp,   0, sizeof(unsigned) * B_SZ * 8);
    cudaMemsetAsync(kflagp,  0, sizeof(unsigned) * B_SZ * 32);
    cudaMemsetAsync(xgflagp, 0, sizeof(unsigned) * B_SZ * 32);

    cudaFuncSetAttribute(mega_kernel,
                         cudaFuncAttributeMaxDynamicSharedMemorySize,
                         SMEM_BYTES);

    mega_kernel<<<384, 384, SMEM_BYTES>>>(x, emb, w_ih, b_ih, w_hh, b_hh,
                                          attn_w, attn_b, comb_w, comb_b,
                                          fc_w, fc_b,
                                          out, out + (size_t)BS * VOC);
}

// round 13
// speedup vs baseline: 1.3480x; 1.0055x over previous
#include <cuda_runtime.h>
#include <math.h>
#include <stdint.h>

#define B_SZ   8
#define S_LEN  2048
#define HID    256
#define EMBD   256
#define VOC    100
#define BS     (B_SZ * S_LEN)
#define G3     768

typedef unsigned long long ull;

// ---------------- packed f32x2 helpers ----------------
__device__ __forceinline__ void fma2(ull& acc, ull a, ull b) {
    asm("fma.rn.f32x2 %0, %1, %2, %0;" : "+l"(acc) : "l"(a), "l"(b));
}
__device__ __forceinline__ ull pk2(float lo, float hi) {
    ull d; asm("mov.b64 %0, {%1, %2};" : "=l"(d) : "f"(lo), "f"(hi)); return d;
}
__device__ __forceinline__ float2 upk2(ull v) {
    float2 r; asm("mov.b64 {%0, %1}, %2;" : "=f"(r.x), "=f"(r.y) : "l"(v)); return r;
}
__device__ __forceinline__ float sigf_(float x) {
    return 1.0f / (1.0f + __expf(-x));
}
__device__ __forceinline__ unsigned ld_acq(const unsigned* p) {
    unsigned v;
    asm volatile("ld.acquire.gpu.global.u32 %0, [%1];" : "=r"(v) : "l"(p) : "memory");
    return v;
}
__device__ __forceinline__ void rel_flag(unsigned* p, unsigned v) {
    asm volatile("fence.acq_rel.gpu;" ::: "memory");
    asm volatile("st.release.gpu.global.u32 [%0], %1;" :: "l"(p), "r"(v) : "memory");
}

// ---------------- scratch ----------------
__device__ float g_xg[BS * G3];
__device__ float g_h[BS * HID];
__device__ float g_keysT[B_SZ * HID * S_LEN];
__device__ unsigned g_prog[B_SZ][8];
__device__ unsigned g_kflag[B_SZ * 32];
__device__ unsigned g_xgflag[B_SZ * 32];   // per (batch, 64-token chunk)

// ---------------------------------------------------------------------------
// k-major microkernel: acc[j][p] += sum_k A[k][i0+2p..] * B[k][j0+j]
// ---------------------------------------------------------------------------
__device__ __forceinline__ void mk_kmajor(const float* __restrict__ At,
                                          const float* __restrict__ Bt,
                                          int i0, int j0, ull (&acc)[4][2])
{
#pragma unroll 4
    for (int k = 0; k < 256; k++) {
        ulonglong2 av = *(const ulonglong2*)(At + k * 68 + i0);
        float4 bv = *(const float4*)(Bt + k * 68 + j0);
        ull b0 = pk2(bv.x, bv.x), b1 = pk2(bv.y, bv.y);
        ull b2 = pk2(bv.z, bv.z), b3 = pk2(bv.w, bv.w);
        fma2(acc[0][0], av.x, b0); fma2(acc[0][1], av.y, b0);
        fma2(acc[1][0], av.x, b1); fma2(acc[1][1], av.y, b1);
        fma2(acc[2][0], av.x, b2); fma2(acc[2][1], av.y, b2);
        fma2(acc[3][0], av.x, b3); fma2(acc[3][1], av.y, b3);
    }
}

// Transpose-load: dst[k][n] (stride 68) from row-major W[rowbase+n][colbase+k]
__device__ __forceinline__ void loadWT(float* __restrict__ dst,
                                       const float* __restrict__ W,
                                       int rowbase, int rs, int colbase, int tid)
{
    const int n0 = (tid & 15) << 2;
    const int kg = (tid >> 4) << 2;
#pragma unroll
    for (int it = 0; it < 4; it++) {
        const int k4 = kg + (it << 6);
        const float* base = W + (size_t)(rowbase + n0) * rs + colbase + k4;
        float4 v0 = *(const float4*)(base);
        float4 v1 = *(const float4*)(base + rs);
        float4 v2 = *(const float4*)(base + 2 * rs);
        float4 v3 = *(const float4*)(base + 3 * rs);
        *(float4*)(dst + (k4 + 0) * 68 + n0) = make_float4(v0.x, v1.x, v2.x, v3.x);
        *(float4*)(dst + (k4 + 1) * 68 + n0) = make_float4(v0.y, v1.y, v2.y, v3.y);
        *(float4*)(dst + (k4 + 2) * 68 + n0) = make_float4(v0.z, v1.z, v2.z, v3.z);
        *(float4*)(dst + (k4 + 3) * 68 + n0) = make_float4(v0.w, v1.w, v2.w, v3.w);
    }
}

// Gathered transpose-load: rows come from emb[xrow[n]] (embedding lookup)
__device__ __forceinline__ void loadA_gather(float* __restrict__ dst,
                                             const float* __restrict__ emb,
                                             const int* __restrict__ xrow, int tid)
{
    const int n0 = (tid & 15) << 2;
    const int kg = (tid >> 4) << 2;
    const int r0 = xrow[n0], r1 = xrow[n0 + 1];
    const int r2 = xrow[n0 + 2], r3 = xrow[n0 + 3];
#pragma unroll
    for (int it = 0; it < 4; it++) {
        const int k4 = kg + (it << 6);
        float4 v0 = *(const float4*)(emb + (size_t)r0 * EMBD + k4);
        float4 v1 = *(const float4*)(emb + (size_t)r1 * EMBD + k4);
        float4 v2 = *(const float4*)(emb + (size_t)r2 * EMBD + k4);
        float4 v3 = *(const float4*)(emb + (size_t)r3 * EMBD + k4);
        *(float4*)(dst + (k4 + 0) * 68 + n0) = make_float4(v0.x, v1.x, v2.x, v3.x);
        *(float4*)(dst + (k4 + 1) * 68 + n0) = make_float4(v0.y, v1.y, v2.y, v3.y);
        *(float4*)(dst + (k4 + 2) * 68 + n0) = make_float4(v0.z, v1.z, v2.z, v3.z);
        *(float4*)(dst + (k4 + 3) * 68 + n0) = make_float4(v0.w, v1.w, v2.w, v3.w);
    }
}

// ---------------------------------------------------------------------------
// MEGA (384 threads): blocks 0..63 GRU; 64..319 workers.
// Workers with qt<8 (blocks 64..127, wave-1 resident) first produce the xg
// chunks for their batch, then do their normal keys/attention/comb/fc work.
// ---------------------------------------------------------------------------
#define OFF_QST 0
#define OFF_KST 17408
#define OFF_VS  34816
#define OFF_SS  51456
#define OFF_RM  55808
#define OFF_RL  55872
#define OFF_RA  55936
#define SMEM_BYTES (56000 * 4)

__global__ void __cluster_dims__(8, 1, 1) __launch_bounds__(384, 1)
mega_kernel(const int* __restrict__ x, const float* __restrict__ emb,
            const float* __restrict__ w_ih, const float* __restrict__ b_ih,
            const float* __restrict__ w_hh, const float* __restrict__ b_hh,
            const float* __restrict__ attn_w, const float* __restrict__ attn_b,
            const float* __restrict__ comb_w, const float* __restrict__ comb_b,
            const float* __restrict__ fc_w, const float* __restrict__ fc_b,
            float* __restrict__ out, float* __restrict__ hid_out)
{
    extern __shared__ float smf[];
    const int tid = threadIdx.x;

    // =============== GRU role (R8 + xg chunk-flag spin) ===============
    if (blockIdx.x < 64) {
        float* hbuf = smf;          // [2 buf][4 part][68]
        float* dots = smf + 544;
        float* xgs  = smf + 640;

        unsigned rank;
        asm("mov.u32 %0, %%cluster_ctarank;" : "=r"(rank));
        const int b = (int)blockIdx.x >> 3;
        const int t = tid;
        const int d = t >> 2;
        const int p = t & 3;
        const int g = d >> 5, jj = d & 31;
        const int grow = (g << 8) + ((int)rank << 5) + jj;

        ull w2[32];
        {
            const ulonglong2* wr =
                (const ulonglong2*)(w_hh + (size_t)grow * 256 + (p << 6));
#pragma unroll
            for (int i = 0; i < 16; i++) {
                ulonglong2 v = wr[i];
                w2[2 * i] = v.x; w2[2 * i + 1] = v.y;
            }
        }
        float bhr = 0.f, bhz = 0.f, bhn = 0.f;
        const int myj = ((int)rank << 5) + t;
        if (t < 32) {
            bhr = b_hh[myj]; bhz = b_hh[256 + myj]; bhn = b_hh[512 + myj];
        }
        for (int i = t; i < 544; i += 384) hbuf[i] = 0.0f;
        __syncthreads();
        asm volatile("barrier.cluster.arrive.aligned;\n\t"
                     "barrier.cluster.wait.aligned;" ::: "memory");

        uint32_t slot0 = 0, slot1 = 0;
        if (t < 32) {
            slot0 = (uint32_t)__cvta_generic_to_shared(
                hbuf + (myj >> 6) * 68 + (myj & 63));
            slot1 = slot0 + 272u * 4u;
        }

        const float* xgbase = g_xg + (size_t)b * S_LEN * G3 + grow;
        float* hb = g_h + (size_t)b * S_LEN * HID;

        float xv = 0.0f;
        if (p == 0) {
            while (!ld_acq(&g_xgflag[b * 32])) __nanosleep(128);
            xv = xgbase[0];
        }

#pragma unroll 1
        for (int s = 0; s < S_LEN; s++) {
            const int cur = s & 1;
            float xvn = 0.0f;
            if (p == 0 && s < S_LEN - 1) {
                const int sn = s + 1;
                if ((sn & 63) == 0) {
                    while (!ld_acq(&g_xgflag[b * 32 + (sn >> 6)]))
                        __nanosleep(128);
                }
                xvn = xgbase[(size_t)sn * G3];
            }

            {
                const ulonglong2* hp =
                    (const ulonglong2*)(hbuf + cur * 272 + p * 68);
                ull a0 = 0ull, a1 = 0ull, a2 = 0ull, a3 = 0ull;
#pragma unroll
                for (int i = 0; i < 8; i++) {
                    ulonglong2 h0 = hp[2 * i], h1 = hp[2 * i + 1];
                    fma2(a0, w2[4 * i + 0], h0.x);
                    fma2(a1, w2[4 * i + 1], h0.y);
                    fma2(a2, w2[4 * i + 2], h1.x);
                    fma2(a3, w2[4 * i + 3], h1.y);
                }
                float2 f0 = upk2(a0), f1 = upk2(a1), f2 = upk2(a2), f3 = upk2(a3);
                float f = ((f0.x + f0.y) + (f1.x + f1.y))
                        + ((f2.x + f2.y) + (f3.x + f3.y));
                f += __shfl_xor_sync(0xffffffffu, f, 1);
                f += __shfl_xor_sync(0xffffffffu, f, 2);
                if (p == 0) { dots[d] = f; xgs[d] = xv; }
            }
            __syncthreads();

            if (t < 32) {
                const float hr = dots[t]      + bhr;
                const float hz = dots[32 + t] + bhz;
                const float hn = dots[64 + t] + bhn;
                const float r = sigf_(xgs[t]      + hr);
                const float z = sigf_(xgs[32 + t] + hz);
                const float a = xgs[64 + t] + r * hn;
                const float n = 2.0f * sigf_(2.0f * a) - 1.0f;
                const float hold = hbuf[cur * 272 + (myj >> 6) * 68 + (myj & 63)];
                const float hnew = (1.0f - z) * n + z * hold;
                hb[(size_t)s * HID + myj] = hnew;
                if (s == S_LEN - 1) hid_out[b * HID + myj] = hnew;
                const uint32_t dst = (cur == 0) ? slot1 : slot0;
#pragma unroll
                for (unsigned r8 = 0; r8 < 8; r8++) {
                    uint32_t ra;
                    asm volatile("mapa.shared::cluster.u32 %0, %1, %2;"
                                 : "=r"(ra) : "r"(dst), "r"(r8));
                    asm volatile("st.shared::cluster.f32 [%0], %1;"
                                 :: "r"(ra), "f"(hnew));
                }
            }
            asm volatile("barrier.cluster.arrive.aligned;\n\t"
                         "barrier.cluster.wait.aligned;" ::: "memory");

            if ((((s + 1) & 31) == 0) && t == 0)
                rel_flag(&g_prog[b][rank], (unsigned)(s + 1));
            xv = xvn;
        }
        return;
    }

    // =============== worker role (R8 + optional xg-producer prologue) ======
    {
        const bool act = (tid < 256);
        const int w  = (int)blockIdx.x - 64;
        const int qt = w >> 3;
        const int b  = w & 7;
        const int tx = tid & 15;
        const int ty = (tid >> 4) & 15;
        const int i0 = ty * 4;
        const int j0 = tx * 4;

        float* QsT = smf + OFF_QST;
        float* KsT = smf + OFF_KST;
        float* Vs  = smf + OFF_VS;
        float* Ss  = smf + OFF_SS;
        float* rm  = smf + OFF_RM;
        float* rl  = smf + OFF_RL;
        float* ra  = smf + OFF_RA;

        const float* Hb = g_h + (size_t)b * S_LEN * HID;
        float* KgT = g_keysT + (size_t)b * HID * S_LEN;

        // ---- xg producer prologue: workers qt<8 (blocks 64..127, wave-1) ----
        if (qt < 8) {
            const int* xb = x + b * S_LEN;
            for (int ch = qt * 4; ch < qt * 4 + 4; ch++) {
                if (act) loadA_gather(QsT, emb, xb + ch * 64, tid);
                __syncthreads();
                for (int nc = 0; nc < 12; nc++) {
                    if (act) loadWT(KsT, w_ih, nc * 64, 256, 0, tid);
                    __syncthreads();
                    if (act) {
                        ull acc[4][2];
#pragma unroll
                        for (int j = 0; j < 4; j++) { acc[j][0] = 0ull; acc[j][1] = 0ull; }
                        mk_kmajor(QsT, KsT, i0, j0, acc);
#pragma unroll
                        for (int j = 0; j < 4; j++) {
                            const int col = nc * 64 + j0 + j;
                            const float bb = b_ih[col];
#pragma unroll
                            for (int p = 0; p < 2; p++) {
                                float2 f = upk2(acc[j][p]);
                                const size_t row =
                                    (size_t)b * S_LEN + ch * 64 + i0 + 2 * p;
                                g_xg[row * G3 + col]       = f.x + bb;
                                g_xg[(row + 1) * G3 + col] = f.y + bb;
                            }
                        }
                    }
                    __syncthreads();
                }
                if (tid == 0) rel_flag(&g_xgflag[b * 32 + ch], 1u);
            }
        }

        // ---- wait for GRU progress ----
        if (tid == 0) {
            const unsigned need = (unsigned)(qt + 1) * 64u;
            for (;;) {
                unsigned m = 0xffffffffu;
#pragma unroll
                for (int r = 0; r < 8; r++) {
                    unsigned v = ld_acq(&g_prog[b][r]);
                    m = (v < m) ? v : m;
                }
                if (m >= need) break;
                __nanosleep(256);
            }
        }
        __syncthreads();

        if (act) loadWT(QsT, Hb, qt * 64, HID, 0, tid);
        __syncthreads();

        // ---- phase 1: keys tile qt ----
        for (int c = 0; c < 4; c++) {
            if (act) loadWT(KsT, attn_w, c * 64, 256, 0, tid);
            __syncthreads();
            if (act) {
                ull acc[4][2];
#pragma unroll
                for (int j = 0; j < 4; j++) { acc[j][0] = 0ull; acc[j][1] = 0ull; }
                mk_kmajor(QsT, KsT, i0, j0, acc);
#pragma unroll
                for (int j = 0; j < 4; j++) {
                    const int ng = c * 64 + j0 + j;
                    const float bb = attn_b[ng];
                    float* dst = KgT + (size_t)ng * S_LEN + qt * 64;
#pragma unroll
                    for (int p = 0; p < 2; p++) {
                        float2 f = upk2(acc[j][p]);
                        dst[i0 + 2 * p + 0] = f.x + bb;
                        dst[i0 + 2 * p + 1] = f.y + bb;
                    }
                }
            }
            __syncthreads();
        }
        if (tid == 0) rel_flag(&g_kflag[b * 32 + qt], 1u);

        // ---- phase 2: causal flash attention ----
        if (tid < 64) { rm[tid] = -1e30f; rl[tid] = 0.0f; }
        ull o2[4][8];
#pragma unroll
        for (int i = 0; i < 4; i++)
#pragma unroll
            for (int q = 0; q < 8; q++) o2[i][q] = 0ull;

        for (int kt = qt; kt >= 0; kt--) {
            const bool diag = (kt == qt);
            if (!diag && tid == 0) {
                while (!ld_acq(&g_kflag[b * 32 + kt])) __nanosleep(256);
            }
            __syncthreads();
            if (act) {
#pragma unroll
                for (int it = 0; it < 16; it++) {
                    const int e = it * 256 + tid;
                    const int k = e >> 4, j4 = (e & 15) << 2;
                    *(float4*)(KsT + k * 68 + j4) =
                        *(const float4*)(KgT + (size_t)k * S_LEN + kt * 64 + j4);
                }
#pragma unroll
                for (int it = 0; it < 16; it++) {
                    const int e = it * 256 + tid;
                    const int r = e >> 6, c4 = (e & 63) << 2;
                    *(float4*)(Vs + r * 260 + c4) =
                        *(const float4*)(Hb + (size_t)(kt * 64 + r) * HID + c4);
                }
            }
            __syncthreads();

            if (act) {
                ull acc[4][2];
#pragma unroll
                for (int j = 0; j < 4; j++) { acc[j][0] = 0ull; acc[j][1] = 0ull; }
                mk_kmajor(QsT, KsT, i0, j0, acc);
#pragma unroll
                for (int j = 0; j < 4; j++)
#pragma unroll
                    for (int p = 0; p < 2; p++) {
                        float2 f = upk2(acc[j][p]);
                        const int il0 = i0 + 2 * p;
                        float v0 = f.x, v1 = f.y;
                        if (diag) {
                            if (j0 + j > il0)     v0 = -1e30f;
                            if (j0 + j > il0 + 1) v1 = -1e30f;
                        }
                        Ss[(il0 + 0) * 68 + j0 + j] = v0;
                        Ss[(il0 + 1) * 68 + j0 + j] = v1;
                    }
            }
            __syncthreads();

            if (act) {
                const int row = tid >> 2, qq = tid & 3;
                float* srow = Ss + row * 68 + qq * 16;
                float4 x0 = *(float4*)(srow + 0);
                float4 x1 = *(float4*)(srow + 4);
                float4 x2 = *(float4*)(srow + 8);
                float4 x3 = *(float4*)(srow + 12);
                const float mo = rm[row];
                float mx = fmaxf(fmaxf(fmaxf(x0.x, x0.y), fmaxf(x0.z, x0.w)),
                                 fmaxf(fmaxf(x1.x, x1.y), fmaxf(x1.z, x1.w)));
                mx = fmaxf(mx, fmaxf(fmaxf(fmaxf(x2.x, x2.y), fmaxf(x2.z, x2.w)),
                                     fmaxf(fmaxf(x3.x, x3.y), fmaxf(x3.z, x3.w))));
                mx = fmaxf(mx, __shfl_xor_sync(0xffffffffu, mx, 1));
                mx = fmaxf(mx, __shfl_xor_sync(0xffffffffu, mx, 2));
                mx = fmaxf(mx, mo);
                x0.x = __expf(x0.x - mx); x0.y = __expf(x0.y - mx);
                x0.z = __expf(x0.z - mx); x0.w = __expf(x0.w - mx);
                x1.x = __expf(x1.x - mx); x1.y = __expf(x1.y - mx);
                x1.z = __expf(x1.z - mx); x1.w = __expf(x1.w - mx);
                x2.x = __expf(x2.x - mx); x2.y = __expf(x2.y - mx);
                x2.z = __expf(x2.z - mx); x2.w = __expf(x2.w - mx);
                x3.x = __expf(x3.x - mx); x3.y = __expf(x3.y - mx);
                x3.z = __expf(x3.z - mx); x3.w = __expf(x3.w - mx);
                float sum = (x0.x + x0.y + x0.z + x0.w)
                          + (x1.x + x1.y + x1.z + x1.w)
                          + (x2.x + x2.y + x2.z + x2.w)
                          + (x3.x + x3.y + x3.z + x3.w);
                *(float4*)(srow + 0)  = x0;
                *(float4*)(srow + 4)  = x1;
                *(float4*)(srow + 8)  = x2;
                *(float4*)(srow + 12) = x3;
                sum += __shfl_xor_sync(0xffffffffu, sum, 1);
                sum += __shfl_xor_sync(0xffffffffu, sum, 2);
                if (qq == 0) {
                    const float al = __expf(mo - mx);
                    rm[row] = mx;
                    rl[row] = rl[row] * al + sum;
                    ra[row] = al;
                }
            }
            __syncthreads();

            if (act) {
#pragma unroll
                for (int i = 0; i < 4; i++) {
                    const float al = ra[i0 + i];
                    const ull ald = pk2(al, al);
#pragma unroll
                    for (int q = 0; q < 8; q++) {
                        ull r2;
                        asm("mul.rn.f32x2 %0, %1, %2;" : "=l"(r2)
                            : "l"(o2[i][q]), "l"(ald));
                        o2[i][q] = r2;
                    }
                }
#pragma unroll 2
                for (int j = 0; j < 64; j++) {
                    ull pd[4];
#pragma unroll
                    for (int i = 0; i < 4; i++) {
                        const float pv = Ss[(i0 + i) * 68 + j];
                        pd[i] = pk2(pv, pv);
                    }
                    const float* vrow = Vs + j * 260 + (tx << 2);
#pragma unroll
                    for (int q = 0; q < 4; q++) {
                        ulonglong2 vv = *(const ulonglong2*)(vrow + (q << 6));
#pragma unroll
                        for (int i = 0; i < 4; i++) {
                            fma2(o2[i][2 * q],     pd[i], vv.x);
                            fma2(o2[i][2 * q + 1], pd[i], vv.y);
                        }
                    }
                }
            }
            __syncthreads();
        }

        // ---- phase 3: normalize, ctx -> Vs ----
        if (act) {
#pragma unroll
            for (int i = 0; i < 4; i++) {
                const float inv = 1.0f / rl[i0 + i];
                float* dst = Vs + (i0 + i) * 260 + (tx << 2);
#pragma unroll
                for (int q = 0; q < 4; q++) {
                    float2 lo = upk2(o2[i][2 * q]);
                    float2 hi = upk2(o2[i][2 * q + 1]);
                    *(float4*)(dst + (q << 6)) =
                        make_float4(lo.x * inv, lo.y * inv, hi.x * inv, hi.y * inv);
                }
            }
        }
        __syncthreads();

        // ---- phase 4: comb(tanh) + fc ----
        float facA[4][4], facB[4][4];
#pragma unroll
        for (int i = 0; i < 4; i++)
#pragma unroll
            for (int j = 0; j < 4; j++) { facA[i][j] = 0.f; facB[i][j] = 0.f; }

        for (int c = 0; c < 4; c++) {
            if (act) loadWT(KsT, comb_w, c * 64, 512, 0, tid);
            __syncthreads();
            ull a1[4][2];
#pragma unroll
            for (int j = 0; j < 4; j++) { a1[j][0] = 0ull; a1[j][1] = 0ull; }
            if (act) mk_kmajor(QsT, KsT, i0, j0, a1);
            __syncthreads();
            if (act) loadWT(KsT, comb_w, c * 64, 512, 256, tid);
            __syncthreads();
            if (act) {
                ull a2[4][4];
#pragma unroll
                for (int i = 0; i < 4; i++)
#pragma unroll
                    for (int j = 0; j < 4; j++) a2[i][j] = 0ull;
#pragma unroll 4
                for (int k = 0; k < 256; k += 2) {
                    ull av[4];
#pragma unroll
                    for (int i = 0; i < 4; i++)
                        av[i] = *(const ull*)(Vs + (i0 + i) * 260 + k);
                    ull bv[4];
#pragma unroll
                    for (int j = 0; j < 4; j++)
                        bv[j] = pk2(KsT[k * 68 + j0 + j], KsT[(k + 1) * 68 + j0 + j]);
#pragma unroll
                    for (int i = 0; i < 4; i++)
#pragma unroll
                        for (int j = 0; j < 4; j++)
                            fma2(a2[i][j], av[i], bv[j]);
                }
#pragma unroll
                for (int j = 0; j < 4; j++) {
                    const float cb = comb_b[c * 64 + j0 + j];
#pragma unroll
                    for (int p = 0; p < 2; p++) {
                        float2 f1 = upk2(a1[j][p]);
                        float2 g0 = upk2(a2[2 * p][j]);
                        float2 g1 = upk2(a2[2 * p + 1][j]);
                        Ss[(i0 + 2 * p) * 68 + j0 + j]     = tanhf(f1.x + g0.x + g0.y + cb);
                        Ss[(i0 + 2 * p + 1) * 68 + j0 + j] = tanhf(f1.y + g1.x + g1.y + cb);
                    }
                }
            }
            __syncthreads();
            for (int e = tid; e < 6400; e += 384) {
                const int v = e >> 6, k = e & 63;
                KsT[k * 105 + v] = fc_w[(size_t)v * 256 + c * 64 + k];
            }
            __syncthreads();
            if (act) {
                ull lA[4][4], lB[4][4];
#pragma unroll
                for (int i = 0; i < 4; i++)
#pragma unroll
                    for (int j = 0; j < 4; j++) { lA[i][j] = 0ull; lB[i][j] = 0ull; }
#pragma unroll 4
                for (int k = 0; k < 64; k += 2) {
                    ull av[4];
#pragma unroll
                    for (int i = 0; i < 4; i++)
                        av[i] = *(const ull*)(Ss + (i0 + i) * 68 + k);
#pragma unroll
                    for (int j = 0; j < 4; j++) {
                        const ull bA = pk2(KsT[k * 105 + j0 + j],
                                           KsT[(k + 1) * 105 + j0 + j]);
                        const ull bB = pk2(KsT[k * 105 + 64 + j0 + j],
                                           KsT[(k + 1) * 105 + 64 + j0 + j]);
#pragma unroll
                        for (int i = 0; i < 4; i++) {
                            fma2(lA[i][j], av[i], bA);
                            fma2(lB[i][j], av[i], bB);
                        }
                    }
                }
#pragma unroll
                for (int i = 0; i < 4; i++)
#pragma unroll
                    for (int j = 0; j < 4; j++) {
                        float2 fa = upk2(lA[i][j]); facA[i][j] += fa.x + fa.y;
                        float2 fb = upk2(lB[i][j]); facB[i][j] += fb.x + fb.y;
                    }
            }
            __syncthreads();
        }

        if (act) {
#pragma unroll
            for (int i = 0; i < 4; i++) {
                const size_t row = (size_t)b * S_LEN + qt * 64 + i0 + i;
#pragma unroll
                for (int j = 0; j < 4; j++) {
                    const int vA = j0 + j;
                    out[row * VOC + vA] = facA[i][j] + fc_b[vA];
                    const int vB = 64 + j0 + j;
                    if (vB < VOC)
                        out[row * VOC + vB] = facB[i][j] + fc_b[vB];
                }
            }
        }
    }
}

// ---------------------------------------------------------------------------
extern "C" void kernel_launch(void* const* d_in, const int* in_sizes, int n_in,
                              void* d_out, int out_size)
{
    const int*   x      = (const int*)  d_in[0];
    const float* emb    = (const float*)d_in[1];
    const float* w_ih   = (const float*)d_in[2];
    const float* w_hh   = (const float*)d_in[3];
    const float* b_ih   = (const float*)d_in[4];
    const float* b_hh   = (const float*)d_in[5];
    const float* attn_w = (const float*)d_in[6];
    const float* attn_b = (const float*)d_in[7];
    const float* comb_w = (const float*)d_in[8];
    const float* comb_b = (const float*)d_in[9];
    const float* fc_w   = (const float*)d_in[10];
    const float* fc_b   = (const float*)d_in[11];
    float* out = (float*)d_out;

    void *progp, *kflagp, *xgflagp;
    cudaGetSymbolAddress(&progp,   g_prog);
    cudaGetSymbolAddress(&kflagp,  g_kflag);
    cudaGetSymbolAddress(&xgflagp, g_xgflag);

    cudaMemsetAsync(progp,   0, sizeof(unsigned) * B_SZ * 8);
    cudaMemsetAsync(kflagp,  0, sizeof(unsigned) * B_SZ * 32);
    cudaMemsetAsync(xgflagp, 0, sizeof(unsigned) * B_SZ * 32);

    cudaFuncSetAttribute(mega_kernel,
                         cudaFuncAttributeMaxDynamicSharedMemorySize,
                         SMEM_BYTES);

    mega_kernel<<<320, 384, SMEM_BYTES>>>(x, emb, w_ih, b_ih, w_hh, b_hh,
                                          attn_w, attn_b, comb_w, comb_b,
                                          fc_w, fc_b,
                                          out, out + (size_t)BS * VOC);
}

// round 14
// speedup vs baseline: 1.5758x; 1.1690x over previous
#include <cuda_runtime.h>
#include <math.h>
#include <stdint.h>

#define B_SZ   8
#define S_LEN  2048
#define HID    256
#define EMBD   256
#define VOC    100
#define BS     (B_SZ * S_LEN)
#define G3     768

typedef unsigned long long ull;

// ---------------- packed f32x2 helpers ----------------
__device__ __forceinline__ void fma2(ull& acc, ull a, ull b) {
    asm("fma.rn.f32x2 %0, %1, %2, %0;" : "+l"(acc) : "l"(a), "l"(b));
}
__device__ __forceinline__ ull pk2(float lo, float hi) {
    ull d; asm("mov.b64 %0, {%1, %2};" : "=l"(d) : "f"(lo), "f"(hi)); return d;
}
__device__ __forceinline__ float2 upk2(ull v) {
    float2 r; asm("mov.b64 {%0, %1}, %2;" : "=f"(r.x), "=f"(r.y) : "l"(v)); return r;
}
__device__ __forceinline__ float sigf_(float x) {
    return 1.0f / (1.0f + __expf(-x));
}
__device__ __forceinline__ unsigned ld_acq(const unsigned* p) {
    unsigned v;
    asm volatile("ld.acquire.gpu.global.u32 %0, [%1];" : "=r"(v) : "l"(p) : "memory");
    return v;
}
__device__ __forceinline__ void rel_flag(unsigned* p, unsigned v) {
    asm volatile("fence.acq_rel.gpu;" ::: "memory");
    asm volatile("st.release.gpu.global.u32 [%0], %1;" :: "l"(p), "r"(v) : "memory");
}

// ---------------- scratch ----------------
__device__ float g_xg[BS * G3];
__device__ float g_h[BS * HID];
__device__ float g_keysT[B_SZ * HID * S_LEN];
__device__ unsigned g_prog[B_SZ][8];
__device__ unsigned g_kflag[B_SZ * 32];

// ---------------------------------------------------------------------------
// SGEMM for xg (proven, used once).
// ---------------------------------------------------------------------------
__global__ void __launch_bounds__(256, 2)
gemm_kernel(const float* __restrict__ A, const int* __restrict__ idx,
            const float* __restrict__ W, const float* __restrict__ bias,
            float* __restrict__ C, int N, int K)
{
    __shared__ __align__(16) float As[8][256];
    __shared__ __align__(16) float Ws[8][128];

    const int bm  = blockIdx.y * 128;
    const int bn  = blockIdx.x * 128;
    const int tid = threadIdx.x;
    const int tx  = tid & 15;
    const int ty  = tid >> 4;
    const int lr  = tid >> 1;
    const int lk  = (tid & 1) << 2;

    ull acc2[8][4];
#pragma unroll
    for (int i = 0; i < 8; i++)
#pragma unroll
        for (int j = 0; j < 4; j++) acc2[i][j] = 0ull;

    int arow = bm + lr;
    if (idx) arow = idx[arow];
    const int wn = bn + lr;

    for (int k0 = 0; k0 < K; k0 += 8) {
        const int kk = k0 + lk;
        float4 av = *(const float4*)(A + (size_t)arow * K + kk);
        *(ull*)&As[lk + 0][2 * lr] = pk2(av.x, av.x);
        *(ull*)&As[lk + 1][2 * lr] = pk2(av.y, av.y);
        *(ull*)&As[lk + 2][2 * lr] = pk2(av.z, av.z);
        *(ull*)&As[lk + 3][2 * lr] = pk2(av.w, av.w);

        float4 wv = make_float4(0.f, 0.f, 0.f, 0.f);
        if (wn < N) wv = *(const float4*)(W + (size_t)wn * K + kk);
        Ws[lk + 0][lr] = wv.x; Ws[lk + 1][lr] = wv.y;
        Ws[lk + 2][lr] = wv.z; Ws[lk + 3][lr] = wv.w;

        __syncthreads();
#pragma unroll
        for (int q = 0; q < 8; q++) {
            ulonglong2 ua0 = *(const ulonglong2*)&As[q][8 * ty];
            ulonglong2 ua1 = *(const ulonglong2*)&As[q][8 * ty + 4];
            ulonglong2 ua2 = *(const ulonglong2*)&As[q][128 + 8 * ty];
            ulonglong2 ua3 = *(const ulonglong2*)&As[q][128 + 8 * ty + 4];
            ulonglong2 ub0 = *(const ulonglong2*)&Ws[q][tx * 4];
            ulonglong2 ub1 = *(const ulonglong2*)&Ws[q][64 + tx * 4];
            ull a2[8] = {ua0.x, ua0.y, ua1.x, ua1.y, ua2.x, ua2.y, ua3.x, ua3.y};
            ull b2[4] = {ub0.x, ub0.y, ub1.x, ub1.y};
#pragma unroll
            for (int i = 0; i < 8; i++)
#pragma unroll
                for (int j = 0; j < 4; j++)
                    fma2(acc2[i][j], a2[i], b2[j]);
        }
        __syncthreads();
    }

#pragma unroll
    for (int i = 0; i < 8; i++) {
        const int r = bm + ((i < 4) ? (ty * 4 + i) : (64 + ty * 4 + i - 4));
        float accr[8];
#pragma unroll
        for (int j = 0; j < 4; j++) {
            float2 f = upk2(acc2[i][j]);
            accr[2 * j] = f.x; accr[2 * j + 1] = f.y;
        }
#pragma unroll
        for (int j = 0; j < 8; j++) {
            const int c = bn + ((j < 4) ? (tx * 4 + j) : (64 + tx * 4 + j - 4));
            if (c < N) C[(size_t)r * N + c] = accr[j] + bias[c];
        }
    }
}

// ---------------------------------------------------------------------------
// k-major microkernel (workers)
// ---------------------------------------------------------------------------
__device__ __forceinline__ void mk_kmajor(const float* __restrict__ At,
                                          const float* __restrict__ Bt,
                                          int i0, int j0, ull (&acc)[4][2])
{
#pragma unroll 4
    for (int k = 0; k < 256; k++) {
        ulonglong2 av = *(const ulonglong2*)(At + k * 68 + i0);
        float4 bv = *(const float4*)(Bt + k * 68 + j0);
        ull b0 = pk2(bv.x, bv.x), b1 = pk2(bv.y, bv.y);
        ull b2 = pk2(bv.z, bv.z), b3 = pk2(bv.w, bv.w);
        fma2(acc[0][0], av.x, b0); fma2(acc[0][1], av.y, b0);
        fma2(acc[1][0], av.x, b1); fma2(acc[1][1], av.y, b1);
        fma2(acc[2][0], av.x, b2); fma2(acc[2][1], av.y, b2);
        fma2(acc[3][0], av.x, b3); fma2(acc[3][1], av.y, b3);
    }
}

__device__ __forceinline__ void loadWT(float* __restrict__ dst,
                                       const float* __restrict__ W,
                                       int rowbase, int rs, int colbase, int tid)
{
    const int n0 = (tid & 15) << 2;
    const int kg = (tid >> 4) << 2;
#pragma unroll
    for (int it = 0; it < 4; it++) {
        const int k4 = kg + (it << 6);
        const float* base = W + (size_t)(rowbase + n0) * rs + colbase + k4;
        float4 v0 = *(const float4*)(base);
        float4 v1 = *(const float4*)(base + rs);
        float4 v2 = *(const float4*)(base + 2 * rs);
        float4 v3 = *(const float4*)(base + 3 * rs);
        *(float4*)(dst + (k4 + 0) * 68 + n0) = make_float4(v0.x, v1.x, v2.x, v3.x);
        *(float4*)(dst + (k4 + 1) * 68 + n0) = make_float4(v0.y, v1.y, v2.y, v3.y);
        *(float4*)(dst + (k4 + 2) * 68 + n0) = make_float4(v0.z, v1.z, v2.z, v3.z);
        *(float4*)(dst + (k4 + 3) * 68 + n0) = make_float4(v0.w, v1.w, v2.w, v3.w);
    }
}

// ---------------------------------------------------------------------------
// MEGA (384 threads): blocks 0..63 GRU; 64..319 workers (R8 structure).
// GRU change vs R8: global h stores moved to warp 11, one step delayed,
// issued at the TOP of each step so they drain during the dot phase.
// ---------------------------------------------------------------------------
#define OFF_QST 0
#define OFF_KST 17408
#define OFF_VS  34816
#define OFF_SS  51456
#define OFF_RM  55808
#define OFF_RL  55872
#define OFF_RA  55936
#define SMEM_BYTES (56000 * 4)

__global__ void __cluster_dims__(8, 1, 1) __launch_bounds__(384, 1)
mega_kernel(const float* __restrict__ xg, const float* __restrict__ w_hh,
            const float* __restrict__ b_hh,
            const float* __restrict__ attn_w, const float* __restrict__ attn_b,
            const float* __restrict__ comb_w, const float* __restrict__ comb_b,
            const float* __restrict__ fc_w, const float* __restrict__ fc_b,
            float* __restrict__ out, float* __restrict__ hid_out)
{
    extern __shared__ float smf[];
    const int tid = threadIdx.x;

    // =============== GRU role ===============
    if (blockIdx.x < 64) {
        float* hbuf = smf;          // [2 buf][4 part][68]
        float* dots = smf + 544;
        float* xgs  = smf + 640;

        unsigned rank;
        asm("mov.u32 %0, %%cluster_ctarank;" : "=r"(rank));
        const int b = (int)blockIdx.x >> 3;
        const int t = tid;
        const int d = t >> 2;
        const int p = t & 3;
        const int g = d >> 5, jj = d & 31;
        const int grow = (g << 8) + ((int)rank << 5) + jj;

        ull w2[32];
        {
            const ulonglong2* wr =
                (const ulonglong2*)(w_hh + (size_t)grow * 256 + (p << 6));
#pragma unroll
            for (int i = 0; i < 16; i++) {
                ulonglong2 v = wr[i];
                w2[2 * i] = v.x; w2[2 * i + 1] = v.y;
            }
        }
        float bhr = 0.f, bhz = 0.f, bhn = 0.f;
        const int myj = ((int)rank << 5) + t;          // gate warp (t<32)
        const int myj11 = ((int)rank << 5) + (t - 352); // store warp (t>=352)
        if (t < 32) {
            bhr = b_hh[myj]; bhz = b_hh[256 + myj]; bhn = b_hh[512 + myj];
        }
        for (int i = t; i < 544; i += 384) hbuf[i] = 0.0f;
        __syncthreads();
        asm volatile("barrier.cluster.arrive.aligned;\n\t"
                     "barrier.cluster.wait.aligned;" ::: "memory");

        uint32_t slot0 = 0, slot1 = 0;
        if (t < 32) {
            slot0 = (uint32_t)__cvta_generic_to_shared(
                hbuf + (myj >> 6) * 68 + (myj & 63));
            slot1 = slot0 + 272u * 4u;
        }

        const float* xgb = xg + (size_t)b * S_LEN * G3 + grow;
        float* hb = g_h + (size_t)b * S_LEN * HID;

        float xv = (p == 0) ? xgb[0] : 0.0f;

#pragma unroll 1
        for (int s = 0; s < S_LEN; s++) {
            const int cur = s & 1;

            // warp 11: store h(s-1) from the stable buffer 'cur' early, so the
            // STG has the whole dot phase to drain before the cluster barrier.
            if (t >= 352 && s > 0) {
                hb[(size_t)(s - 1) * HID + myj11] =
                    hbuf[cur * 272 + (myj11 >> 6) * 68 + (myj11 & 63)];
            }

            float xvn = 0.0f;
            if (p == 0 && s < S_LEN - 1)
                xvn = xgb[(size_t)(s + 1) * G3];

            {
                const ulonglong2* hp =
                    (const ulonglong2*)(hbuf + cur * 272 + p * 68);
                ull a0 = 0ull, a1 = 0ull, a2 = 0ull, a3 = 0ull;
#pragma unroll
                for (int i = 0; i < 8; i++) {
                    ulonglong2 h0 = hp[2 * i], h1 = hp[2 * i + 1];
                    fma2(a0, w2[4 * i + 0], h0.x);
                    fma2(a1, w2[4 * i + 1], h0.y);
                    fma2(a2, w2[4 * i + 2], h1.x);
                    fma2(a3, w2[4 * i + 3], h1.y);
                }
                float2 f0 = upk2(a0), f1 = upk2(a1), f2 = upk2(a2), f3 = upk2(a3);
                float f = ((f0.x + f0.y) + (f1.x + f1.y))
                        + ((f2.x + f2.y) + (f3.x + f3.y));
                f += __shfl_xor_sync(0xffffffffu, f, 1);
                f += __shfl_xor_sync(0xffffffffu, f, 2);
                if (p == 0) { dots[d] = f; xgs[d] = xv; }
            }
            __syncthreads();

            if (t < 32) {
                const float hr = dots[t]      + bhr;
                const float hz = dots[32 + t] + bhz;
                const float hn = dots[64 + t] + bhn;
                const float r = sigf_(xgs[t]      + hr);
                const float z = sigf_(xgs[32 + t] + hz);
                const float a = xgs[64 + t] + r * hn;
                const float n = 2.0f * sigf_(2.0f * a) - 1.0f;
                const float hold = hbuf[cur * 272 + (myj >> 6) * 68 + (myj & 63)];
                const float hnew = (1.0f - z) * n + z * hold;
                const uint32_t dst = (cur == 0) ? slot1 : slot0;
#pragma unroll
                for (unsigned r8 = 0; r8 < 8; r8++) {
                    uint32_t ra;
                    asm volatile("mapa.shared::cluster.u32 %0, %1, %2;"
                                 : "=r"(ra) : "r"(dst), "r"(r8));
                    asm volatile("st.shared::cluster.f32 [%0], %1;"
                                 :: "r"(ra), "f"(hnew));
                }
            }
            asm volatile("barrier.cluster.arrive.aligned;\n\t"
                         "barrier.cluster.wait.aligned;" ::: "memory");

            // publish value s: rows <= s-1 are in global (stored during steps<=s)
            if (((s & 31) == 0) && s > 0 && t == 0)
                rel_flag(&g_prog[b][rank], (unsigned)s);
            xv = xvn;
        }

        // epilogue: row 2047 lives in buffer (S_LEN)&1 == 0
        if (t >= 352) {
            const float hl = hbuf[(myj11 >> 6) * 68 + (myj11 & 63)];
            hb[(size_t)(S_LEN - 1) * HID + myj11] = hl;
            hid_out[b * HID + myj11] = hl;
        }
        __syncthreads();
        if (t == 0) rel_flag(&g_prog[b][rank], (unsigned)S_LEN);
        return;
    }

    // =============== worker role (R8, unchanged; threads 0..255) ===========
    {
        const bool act = (tid < 256);
        const int w  = (int)blockIdx.x - 64;
        const int qt = w >> 3;
        const int b  = w & 7;
        const int tx = tid & 15;
        const int ty = (tid >> 4) & 15;
        const int i0 = ty * 4;
        const int j0 = tx * 4;

        float* QsT = smf + OFF_QST;
        float* KsT = smf + OFF_KST;
        float* Vs  = smf + OFF_VS;
        float* Ss  = smf + OFF_SS;
        float* rm  = smf + OFF_RM;
        float* rl  = smf + OFF_RL;
        float* ra  = smf + OFF_RA;

        const float* Hb = g_h + (size_t)b * S_LEN * HID;
        float* KgT = g_keysT + (size_t)b * HID * S_LEN;

        if (tid == 0) {
            const unsigned need = (unsigned)(qt + 1) * 64u;
            for (;;) {
                unsigned m = 0xffffffffu;
#pragma unroll
                for (int r = 0; r < 8; r++) {
                    unsigned v = ld_acq(&g_prog[b][r]);
                    m = (v < m) ? v : m;
                }
                if (m >= need) break;
                __nanosleep(256);
            }
        }
        __syncthreads();

        if (act) loadWT(QsT, Hb, qt * 64, HID, 0, tid);
        __syncthreads();

        // ---- phase 1: keys tile qt ----
        for (int c = 0; c < 4; c++) {
            if (act) loadWT(KsT, attn_w, c * 64, 256, 0, tid);
            __syncthreads();
            if (act) {
                ull acc[4][2];
#pragma unroll
                for (int j = 0; j < 4; j++) { acc[j][0] = 0ull; acc[j][1] = 0ull; }
                mk_kmajor(QsT, KsT, i0, j0, acc);
#pragma unroll
                for (int j = 0; j < 4; j++) {
                    const int ng = c * 64 + j0 + j;
                    const float bb = attn_b[ng];
                    float* dst = KgT + (size_t)ng * S_LEN + qt * 64;
#pragma unroll
                    for (int p = 0; p < 2; p++) {
                        float2 f = upk2(acc[j][p]);
                        dst[i0 + 2 * p + 0] = f.x + bb;
                        dst[i0 + 2 * p + 1] = f.y + bb;
                    }
                }
            }
            __syncthreads();
        }
        if (tid == 0) rel_flag(&g_kflag[b * 32 + qt], 1u);

        // ---- phase 2: causal flash attention ----
        if (tid < 64) { rm[tid] = -1e30f; rl[tid] = 0.0f; }
        ull o2[4][8];
#pragma unroll
        for (int i = 0; i < 4; i++)
#pragma unroll
            for (int q = 0; q < 8; q++) o2[i][q] = 0ull;

        for (int kt = qt; kt >= 0; kt--) {
            const bool diag = (kt == qt);
            if (!diag && tid == 0) {
                while (!ld_acq(&g_kflag[b * 32 + kt])) __nanosleep(256);
            }
            __syncthreads();
            if (act) {
#pragma unroll
                for (int it = 0; it < 16; it++) {
                    const int e = it * 256 + tid;
                    const int k = e >> 4, j4 = (e & 15) << 2;
                    *(float4*)(KsT + k * 68 + j4) =
                        *(const float4*)(KgT + (size_t)k * S_LEN + kt * 64 + j4);
                }
#pragma unroll
                for (int it = 0; it < 16; it++) {
                    const int e = it * 256 + tid;
                    const int r = e >> 6, c4 = (e & 63) << 2;
                    *(float4*)(Vs + r * 260 + c4) =
                        *(const float4*)(Hb + (size_t)(kt * 64 + r) * HID + c4);
                }
            }
            __syncthreads();

            if (act) {
                ull acc[4][2];
#pragma unroll
                for (int j = 0; j < 4; j++) { acc[j][0] = 0ull; acc[j][1] = 0ull; }
                mk_kmajor(QsT, KsT, i0, j0, acc);
#pragma unroll
                for (int j = 0; j < 4; j++)
#pragma unroll
                    for (int p = 0; p < 2; p++) {
                        float2 f = upk2(acc[j][p]);
                        const int il0 = i0 + 2 * p;
                        float v0 = f.x, v1 = f.y;
                        if (diag) {
                            if (j0 + j > il0)     v0 = -1e30f;
                            if (j0 + j > il0 + 1) v1 = -1e30f;
                        }
                        Ss[(il0 + 0) * 68 + j0 + j] = v0;
                        Ss[(il0 + 1) * 68 + j0 + j] = v1;
                    }
            }
            __syncthreads();

            if (act) {
                const int row = tid >> 2, qq = tid & 3;
                float* srow = Ss + row * 68 + qq * 16;
                float4 x0 = *(float4*)(srow + 0);
                float4 x1 = *(float4*)(srow + 4);
                float4 x2 = *(float4*)(srow + 8);
                float4 x3 = *(float4*)(srow + 12);
                const float mo = rm[row];
                float mx = fmaxf(fmaxf(fmaxf(x0.x, x0.y), fmaxf(x0.z, x0.w)),
                                 fmaxf(fmaxf(x1.x, x1.y), fmaxf(x1.z, x1.w)));
                mx = fmaxf(mx, fmaxf(fmaxf(fmaxf(x2.x, x2.y), fmaxf(x2.z, x2.w)),
                                     fmaxf(fmaxf(x3.x, x3.y), fmaxf(x3.z, x3.w))));
                mx = fmaxf(mx, __shfl_xor_sync(0xffffffffu, mx, 1));
                mx = fmaxf(mx, __shfl_xor_sync(0xffffffffu, mx, 2));
                mx = fmaxf(mx, mo);
                x0.x = __expf(x0.x - mx); x0.y = __expf(x0.y - mx);
                x0.z = __expf(x0.z - mx); x0.w = __expf(x0.w - mx);
                x1.x = __expf(x1.x - mx); x1.y = __expf(x1.y - mx);
                x1.z = __expf(x1.z - mx); x1.w = __expf(x1.w - mx);
                x2.x = __expf(x2.x - mx); x2.y = __expf(x2.y - mx);
                x2.z = __expf(x2.z - mx); x2.w = __expf(x2.w - mx);
                x3.x = __expf(x3.x - mx); x3.y = __expf(x3.y - mx);
                x3.z = __expf(x3.z - mx); x3.w = __expf(x3.w - mx);
                float sum = (x0.x + x0.y + x0.z + x0.w)
                          + (x1.x + x1.y + x1.z + x1.w)
                          + (x2.x + x2.y + x2.z + x2.w)
                          + (x3.x + x3.y + x3.z + x3.w);
                *(float4*)(srow + 0)  = x0;
                *(float4*)(srow + 4)  = x1;
                *(float4*)(srow + 8)  = x2;
                *(float4*)(srow + 12) = x3;
                sum += __shfl_xor_sync(0xffffffffu, sum, 1);
                sum += __shfl_xor_sync(0xffffffffu, sum, 2);
                if (qq == 0) {
                    const float al = __expf(mo - mx);
                    rm[row] = mx;
                    rl[row] = rl[row] * al + sum;
                    ra[row] = al;
                }
            }
            __syncthreads();

            if (act) {
#pragma unroll
                for (int i = 0; i < 4; i++) {
                    const float al = ra[i0 + i];
                    const ull ald = pk2(al, al);
#pragma unroll
                    for (int q = 0; q < 8; q++) {
                        ull r2;
                        asm("mul.rn.f32x2 %0, %1, %2;" : "=l"(r2)
                            : "l"(o2[i][q]), "l"(ald));
                        o2[i][q] = r2;
                    }
                }
#pragma unroll 2
                for (int j = 0; j < 64; j++) {
                    ull pd[4];
#pragma unroll
                    for (int i = 0; i < 4; i++) {
                        const float pv = Ss[(i0 + i) * 68 + j];
                        pd[i] = pk2(pv, pv);
                    }
                    const float* vrow = Vs + j * 260 + (tx << 2);
#pragma unroll
                    for (int q = 0; q < 4; q++) {
                        ulonglong2 vv = *(const ulonglong2*)(vrow + (q << 6));
#pragma unroll
                        for (int i = 0; i < 4; i++) {
                            fma2(o2[i][2 * q],     pd[i], vv.x);
                            fma2(o2[i][2 * q + 1], pd[i], vv.y);
                        }
                    }
                }
            }
            __syncthreads();
        }

        // ---- phase 3: normalize, ctx -> Vs ----
        if (act) {
#pragma unroll
            for (int i = 0; i < 4; i++) {
                const float inv = 1.0f / rl[i0 + i];
                float* dst = Vs + (i0 + i) * 260 + (tx << 2);
#pragma unroll
                for (int q = 0; q < 4; q++) {
                    float2 lo = upk2(o2[i][2 * q]);
                    float2 hi = upk2(o2[i][2 * q + 1]);
                    *(float4*)(dst + (q << 6)) =
                        make_float4(lo.x * inv, lo.y * inv, hi.x * inv, hi.y * inv);
                }
            }
        }
        __syncthreads();

        // ---- phase 4: comb(tanh) + fc ----
        float facA[4][4], facB[4][4];
#pragma unroll
        for (int i = 0; i < 4; i++)
#pragma unroll
            for (int j = 0; j < 4; j++) { facA[i][j] = 0.f; facB[i][j] = 0.f; }

        for (int c = 0; c < 4; c++) {
            if (act) loadWT(KsT, comb_w, c * 64, 512, 0, tid);
            __syncthreads();
            ull a1[4][2];
#pragma unroll
            for (int j = 0; j < 4; j++) { a1[j][0] = 0ull; a1[j][1] = 0ull; }
            if (act) mk_kmajor(QsT, KsT, i0, j0, a1);
            __syncthreads();
            if (act) loadWT(KsT, comb_w, c * 64, 512, 256, tid);
            __syncthreads();
            if (act) {
                ull a2[4][4];
#pragma unroll
                for (int i = 0; i < 4; i++)
#pragma unroll
                    for (int j = 0; j < 4; j++) a2[i][j] = 0ull;
#pragma unroll 4
                for (int k = 0; k < 256; k += 2) {
                    ull av[4];
#pragma unroll
                    for (int i = 0; i < 4; i++)
                        av[i] = *(const ull*)(Vs + (i0 + i) * 260 + k);
                    ull bv[4];
#pragma unroll
                    for (int j = 0; j < 4; j++)
                        bv[j] = pk2(KsT[k * 68 + j0 + j], KsT[(k + 1) * 68 + j0 + j]);
#pragma unroll
                    for (int i = 0; i < 4; i++)
#pragma unroll
                        for (int j = 0; j < 4; j++)
                            fma2(a2[i][j], av[i], bv[j]);
                }
#pragma unroll
                for (int j = 0; j < 4; j++) {
                    const float cb = comb_b[c * 64 + j0 + j];
#pragma unroll
                    for (int p = 0; p < 2; p++) {
                        float2 f1 = upk2(a1[j][p]);
                        float2 g0 = upk2(a2[2 * p][j]);
                        float2 g1 = upk2(a2[2 * p + 1][j]);
                        Ss[(i0 + 2 * p) * 68 + j0 + j]     = tanhf(f1.x + g0.x + g0.y + cb);
                        Ss[(i0 + 2 * p + 1) * 68 + j0 + j] = tanhf(f1.y + g1.x + g1.y + cb);
                    }
                }
            }
            __syncthreads();
            for (int e = tid; e < 6400; e += 384) {
                const int v = e >> 6, k = e & 63;
                KsT[k * 105 + v] = fc_w[(size_t)v * 256 + c * 64 + k];
            }
            __syncthreads();
            if (act) {
                ull lA[4][4], lB[4][4];
#pragma unroll
                for (int i = 0; i < 4; i++)
#pragma unroll
                    for (int j = 0; j < 4; j++) { lA[i][j] = 0ull; lB[i][j] = 0ull; }
#pragma unroll 4
                for (int k = 0; k < 64; k += 2) {
                    ull av[4];
#pragma unroll
                    for (int i = 0; i < 4; i++)
                        av[i] = *(const ull*)(Ss + (i0 + i) * 68 + k);
#pragma unroll
                    for (int j = 0; j < 4; j++) {
                        const ull bA = pk2(KsT[k * 105 + j0 + j],
                                           KsT[(k + 1) * 105 + j0 + j]);
                        const ull bB = pk2(KsT[k * 105 + 64 + j0 + j],
                                           KsT[(k + 1) * 105 + 64 + j0 + j]);
#pragma unroll
                        for (int i = 0; i < 4; i++) {
                            fma2(lA[i][j], av[i], bA);
                            fma2(lB[i][j], av[i], bB);
                        }
                    }
                }
#pragma unroll
                for (int i = 0; i < 4; i++)
#pragma unroll
                    for (int j = 0; j < 4; j++) {
                        float2 fa = upk2(lA[i][j]); facA[i][j] += fa.x + fa.y;
                        float2 fb = upk2(lB[i][j]); facB[i][j] += fb.x + fb.y;
                    }
            }
            __syncthreads();
        }

        if (act) {
#pragma unroll
            for (int i = 0; i < 4; i++) {
                const size_t row = (size_t)b * S_LEN + qt * 64 + i0 + i;
#pragma unroll
                for (int j = 0; j < 4; j++) {
                    const int vA = j0 + j;
                    out[row * VOC + vA] = facA[i][j] + fc_b[vA];
                    const int vB = 64 + j0 + j;
                    if (vB < VOC)
                        out[row * VOC + vB] = facB[i][j] + fc_b[vB];
                }
            }
        }
    }
}

// ---------------------------------------------------------------------------
extern "C" void kernel_launch(void* const* d_in, const int* in_sizes, int n_in,
                              void* d_out, int out_size)
{
    const int*   x      = (const int*)  d_in[0];
    const float* emb    = (const float*)d_in[1];
    const float* w_ih   = (const float*)d_in[2];
    const float* w_hh   = (const float*)d_in[3];
    const float* b_ih   = (const float*)d_in[4];
    const float* b_hh   = (const float*)d_in[5];
    const float* attn_w = (const float*)d_in[6];
    const float* attn_b = (const float*)d_in[7];
    const float* comb_w = (const float*)d_in[8];
    const float* comb_b = (const float*)d_in[9];
    const float* fc_w   = (const float*)d_in[10];
    const float* fc_b   = (const float*)d_in[11];
    float* out = (float*)d_out;

    float* xg;
    void *progp, *kflagp;
    cudaGetSymbolAddress((void**)&xg, g_xg);
    cudaGetSymbolAddress(&progp,  g_prog);
    cudaGetSymbolAddress(&kflagp, g_kflag);

    cudaMemsetAsync(progp,  0, sizeof(unsigned) * B_SZ * 8);
    cudaMemsetAsync(kflagp, 0, sizeof(unsigned) * B_SZ * 32);

    cudaFuncSetAttribute(mega_kernel,
                         cudaFuncAttributeMaxDynamicSharedMemorySize,
                         SMEM_BYTES);

    gemm_kernel<<<dim3(6, 128), 256>>>(emb, x, w_ih, b_ih, xg, G3, EMBD);

    mega_kernel<<<320, 384, SMEM_BYTES>>>(xg, w_hh, b_hh,
                                          attn_w, attn_b, comb_w, comb_b,
                                          fc_w, fc_b,
                                          out, out + (size_t)BS * VOC);
}